// round 9
// baseline (speedup 1.0000x reference)
#include <cuda_runtime.h>
#include <cuda_fp16.h>
#include <cstdint>
#include <math.h>

#define NB 4
#define NS 2048
#define NHID 4096
#define NH 32
#define ND 128
#define NTOK (NB*NS)
#define MLPDIM (3*NHID)

// ---------------- scratch ----------------
__device__ __half  d_X16 [(size_t)NTOK*NHID];
__device__ __half  d_Wk16[(size_t)NHID*NHID];
__device__ __half  d_Wv16[(size_t)NHID*NHID];
__device__ __half  d_K16 [(size_t)NTOK*NHID];
__device__ __half  d_V16 [(size_t)NTOK*NHID];
__device__ float2  d_cs  [NS*64];
__device__ float   d_scores[NB*NH*NS];
__device__ float   d_attn  [NB*NH*NS];
__device__ float   d_attnv_part[8][NB*NH*ND];
__device__ float   d_attn_out[NB*NHID];
__device__ float   d_y1 [NB*NHID];
__device__ float   d_ln1[NB*NHID];
__device__ float   d_cbuf[NB*MLPDIM];
__device__ float   d_y2 [NB*NHID];
__device__ float   d_ln2[NB*NHID];

// ---------------- helpers ----------------
__device__ __forceinline__ float warp_sum_all(float v) {
    #pragma unroll
    for (int o = 16; o > 0; o >>= 1) v += __shfl_xor_sync(0xffffffffu, v, o);
    return v;
}
__device__ __forceinline__ float warp_max_all(float v) {
    #pragma unroll
    for (int o = 16; o > 0; o >>= 1) v = fmaxf(v, __shfl_xor_sync(0xffffffffu, v, o));
    return v;
}
__device__ __forceinline__ uint32_t smem_u32(const void* p) {
    return (uint32_t)__cvta_generic_to_shared(p);
}

// ==================== HMMA GEMM (fused K+V): C = X * W^T ====================
// CTA 128x128, 4 warps (warp tile 64x64), BK=128 (32 iterations),
// coalesced synchronous LDG->STS (R8 pattern), 2 CTAs/SM.
// blockIdx.z: 0 -> K16 (plain), 1 -> V16 (RoPE fused in epilogue).
#define BM 128
#define BN 128
#define BK 128
#define LDSH 136                          // halves per smem row (128 + 8 pad)
#define RPB (LDSH*2)                      // 272 bytes per row
#define TILE_B (BM*RPB)                   // 34816 bytes per tile
#define GEMM_SMEM (2*TILE_B)              // 69632 bytes (A + B)
#define KCH (NHID/BK)                     // 32 iterations

__global__ void __launch_bounds__(128, 2) gemm_kv() {
    extern __shared__ __half sm[];        // A tile then B tile

    const int z = blockIdx.z;
    const __half* __restrict__ Aptr = d_X16;
    const __half* __restrict__ Bptr = z ? d_Wv16 : d_Wk16;
    __half* __restrict__ Cptr       = z ? d_V16  : d_K16;

    const int t = threadIdx.x;
    const int lane = t & 31, w = t >> 5;
    const int wm = w >> 1, wn = w & 1;            // 2 x 2 warps, 64x64 each
    const int bm = blockIdx.y * BM, bn = blockIdx.x * BN;

    float acc[4][8][4];
    #pragma unroll
    for (int a = 0; a < 4; a++)
        #pragma unroll
        for (int b = 0; b < 8; b++)
            #pragma unroll
            for (int c = 0; c < 4; c++) acc[a][b][c] = 0.f;

    // ---- coalesced load geometry: 16 threads/row (256B = 2 lines), 8 rows/pass ----
    const int lrow = t >> 4, lch = t & 15;        // rows 0..7, chunks 0..15 (16B)
    const __half* Ag = Aptr + (size_t)(bm + lrow) * NHID + lch * 8;
    const __half* Bg = Bptr + (size_t)(bn + lrow) * NHID + lch * 8;
    __half* Asp = &sm[lrow * LDSH + lch * 8];
    __half* Bsp = &sm[BM * LDSH + lrow * LDSH + lch * 8];

    // per-warp ldmatrix byte offsets
    const uint32_t sbase = smem_u32(sm);
    const uint32_t a_off = (wm * 64 + (lane & 15)) * RPB + ((lane >> 4) << 4);
    const uint32_t b_off = (uint32_t)TILE_B
                         + (wn * 64 + (lane & 7) + ((lane >> 4) << 3)) * RPB
                         + ((lane & 8) << 1);

    for (int k0 = 0; k0 < NHID; k0 += BK) {
        // ---- synchronous coalesced fill (16 passes x 8 rows per tile) ----
        #pragma unroll
        for (int r = 0; r < 16; r++) {
            *(float4*)(Asp + r * 8 * LDSH) = *(const float4*)(Ag + (size_t)r * 8 * NHID + k0);
            *(float4*)(Bsp + r * 8 * LDSH) = *(const float4*)(Bg + (size_t)r * 8 * NHID + k0);
        }
        __syncthreads();

        #pragma unroll
        for (int kk = 0; kk < 8; kk++) {
            uint32_t af[4][4], bf[4][4];
            #pragma unroll
            for (int mi = 0; mi < 4; mi++) {
                uint32_t addr = sbase + a_off + mi * (16 * RPB) + kk * 32;
                asm volatile("ldmatrix.sync.aligned.m8n8.x4.shared.b16 {%0,%1,%2,%3}, [%4];"
                    : "=r"(af[mi][0]), "=r"(af[mi][1]), "=r"(af[mi][2]), "=r"(af[mi][3])
                    : "r"(addr));
            }
            #pragma unroll
            for (int nb = 0; nb < 4; nb++) {
                uint32_t addr = sbase + b_off + nb * (16 * RPB) + kk * 32;
                asm volatile("ldmatrix.sync.aligned.m8n8.x4.shared.b16 {%0,%1,%2,%3}, [%4];"
                    : "=r"(bf[nb][0]), "=r"(bf[nb][1]), "=r"(bf[nb][2]), "=r"(bf[nb][3])
                    : "r"(addr));
            }
            #pragma unroll
            for (int mi = 0; mi < 4; mi++)
                #pragma unroll
                for (int ni = 0; ni < 8; ni++) {
                    uint32_t b0 = bf[ni >> 1][(ni & 1) * 2];
                    uint32_t b1 = bf[ni >> 1][(ni & 1) * 2 + 1];
                    asm volatile(
                        "mma.sync.aligned.m16n8k16.row.col.f32.f16.f16.f32 "
                        "{%0,%1,%2,%3}, {%4,%5,%6,%7}, {%8,%9}, {%0,%1,%2,%3};"
                        : "+f"(acc[mi][ni][0]), "+f"(acc[mi][ni][1]),
                          "+f"(acc[mi][ni][2]), "+f"(acc[mi][ni][3])
                        : "r"(af[mi][0]), "r"(af[mi][1]), "r"(af[mi][2]), "r"(af[mi][3]),
                          "r"(b0), "r"(b1));
                }
        }
        __syncthreads();
    }

    // ---- epilogue (RoPE fused for V) ----
    #pragma unroll
    for (int mi = 0; mi < 4; mi++) {
        int r0 = bm + wm * 64 + mi * 16 + (lane >> 2);
        int s0 = r0 & (NS - 1), s1 = (r0 + 8) & (NS - 1);
        #pragma unroll
        for (int ni = 0; ni < 8; ni++) {
            int cc = bn + wn * 64 + ni * 8 + ((lane & 3) << 1);
            float v0 = acc[mi][ni][0], v1 = acc[mi][ni][1];
            float v2 = acc[mi][ni][2], v3 = acc[mi][ni][3];
            if (z) {
                int j = (cc & 127) >> 1;
                float2 cs0 = d_cs[s0 * 64 + j];
                float2 cs1 = d_cs[s1 * 64 + j];
                float t0 = v0*cs0.x - v1*cs0.y;
                float t1 = v1*cs0.x + v0*cs0.y;
                float t2 = v2*cs1.x - v3*cs1.y;
                float t3 = v3*cs1.x + v2*cs1.y;
                v0 = t0; v1 = t1; v2 = t2; v3 = t3;
            }
            *(__half2*)(Cptr + (size_t)r0 * NHID + cc)       = __floats2half2_rn(v0, v1);
            *(__half2*)(Cptr + (size_t)(r0 + 8) * NHID + cc) = __floats2half2_rn(v2, v3);
        }
    }
}

// ---------------- fp32 -> fp16 conversion ----------------
__global__ void __launch_bounds__(256) cvt_all(const float* __restrict__ X,
                                               const float* __restrict__ Wk,
                                               const float* __restrict__ Wv) {
    int i = blockIdx.x * 256 + threadIdx.x;
    const float* src; __half* dst; int j;
    if (i < 8388608)        { src = X;  dst = d_X16;  j = i; }
    else if (i < 12582912)  { src = Wk; dst = d_Wk16; j = i - 8388608; }
    else                    { src = Wv; dst = d_Wv16; j = i - 12582912; }
    float4 v = *(const float4*)(src + (size_t)j * 4);
    __half2* o = (__half2*)(dst + (size_t)j * 4);
    o[0] = __floats2half2_rn(v.x, v.y);
    o[1] = __floats2half2_rn(v.z, v.w);
}

// ---------------- RoPE cos/sin table ----------------
__global__ void __launch_bounds__(256) cs_kernel() {
    int i = blockIdx.x * 256 + threadIdx.x;
    if (i >= NS * 64) return;
    int s = i >> 6, j = i & 63;
    float theta = powf(10000.f, -2.f * (float)j / 128.f);
    float sv, cv;
    sincosf((float)s * theta, &sv, &cv);
    d_cs[i] = make_float2(cv, sv);
}

// ---------------- scores[b,h,s] = (R_s^T q_h) . K[b,s,h,:] ----------------
__global__ void __launch_bounds__(256) scores_kernel(const float* __restrict__ q) {
    int task = blockIdx.x * 8 + (threadIdx.x >> 5);
    int lane = threadIdx.x & 31;
    int bs = task >> 5, h = task & 31;
    int s  = bs & (NS - 1);
    const __half* kp = d_K16 + (size_t)bs * NHID + h * ND + lane * 4;
    __half2 ka = *(const __half2*)kp;
    __half2 kb = *(const __half2*)(kp + 2);
    float2 cs0 = d_cs[s * 64 + lane * 2];
    float2 cs1 = d_cs[s * 64 + lane * 2 + 1];
    const float* qp = q + h * ND + lane * 4;
    float q0 = __ldg(qp), q1 = __ldg(qp+1), q2 = __ldg(qp+2), q3 = __ldg(qp+3);
    float sum = (q0*cs0.x + q1*cs0.y) * __low2float(ka)
              + (q1*cs0.x - q0*cs0.y) * __high2float(ka)
              + (q2*cs1.x + q3*cs1.y) * __low2float(kb)
              + (q3*cs1.x - q2*cs1.y) * __high2float(kb);
    sum = warp_sum_all(sum);
    if (lane == 0) {
        int b = bs >> 11;
        d_scores[((b * NH + h) << 11) + s] = sum;
    }
}

// ---------------- softmax over s ----------------
__global__ void __launch_bounds__(256) softmax_kernel() {
    int bh = blockIdx.x;
    const float* sc = d_scores + (size_t)bh * NS;
    float* at = d_attn + (size_t)bh * NS;
    float v[8]; float m = -1e30f;
    #pragma unroll
    for (int i = 0; i < 8; i++) { v[i] = sc[threadIdx.x + i*256]; m = fmaxf(m, v[i]); }
    m = warp_max_all(m);
    __shared__ float r[8];
    int wid = threadIdx.x >> 5;
    if ((threadIdx.x & 31) == 0) r[wid] = m;
    __syncthreads();
    if (threadIdx.x == 0) { float t = r[0]; for (int w = 1; w < 8; w++) t = fmaxf(t, r[w]); r[0] = t; }
    __syncthreads();
    m = r[0];
    float tot = 0.f;
    #pragma unroll
    for (int i = 0; i < 8; i++) { v[i] = expf(v[i] - m); tot += v[i]; }
    tot = warp_sum_all(tot);
    __syncthreads();
    if ((threadIdx.x & 31) == 0) r[wid] = tot;
    __syncthreads();
    if (threadIdx.x == 0) { float t = 0; for (int w = 0; w < 8; w++) t += r[w]; r[0] = t; }
    __syncthreads();
    float inv = 1.f / r[0];
    #pragma unroll
    for (int i = 0; i < 8; i++) at[threadIdx.x + i*256] = v[i] * inv;
}

// ---------------- attn @ V (split-K) ----------------
__global__ void __launch_bounds__(128) attnv_kernel() {
    int bh = blockIdx.x, ch = blockIdx.y;
    int b = bh >> 5, h = bh & 31;
    const float* at = d_attn + (size_t)bh * NS + ch * 256;
    const __half* vp = d_V16 + (size_t)(b * NS + ch * 256) * NHID + h * ND + threadIdx.x;
    float acc = 0.f;
    #pragma unroll 8
    for (int i = 0; i < 256; i++)
        acc += at[i] * __half2float(vp[(size_t)i * NHID]);
    d_attnv_part[ch][bh * ND + threadIdx.x] = acc;
}
__global__ void __launch_bounds__(256) attnv_reduce() {
    int i = blockIdx.x * 256 + threadIdx.x;
    float s = 0.f;
    #pragma unroll
    for (int c = 0; c < 8; c++) s += d_attnv_part[c][i];
    d_attn_out[i] = s;
}

// ---------------- 4-row GEMV (float4 weight loads) ----------------
__device__ __forceinline__ void gemv4_body(const float* __restrict__ W, const float* __restrict__ x,
                                           float* __restrict__ y, const float* __restrict__ bias,
                                           int K, int N) {
    int i = blockIdx.x;
    const float4* w4 = (const float4*)(W + (size_t)i * K);
    const float4* x4 = (const float4*)x;
    int K4 = K >> 2;
    float a0 = 0, a1 = 0, a2 = 0, a3 = 0;
    for (int k = threadIdx.x; k < K4; k += 256) {
        float4 wv = __ldg(w4 + k);
        float4 v0 = __ldg(x4 + k);
        float4 v1 = __ldg(x4 + K4 + k);
        float4 v2 = __ldg(x4 + 2*K4 + k);
        float4 v3 = __ldg(x4 + 3*K4 + k);
        a0 += wv.x*v0.x + wv.y*v0.y + wv.z*v0.z + wv.w*v0.w;
        a1 += wv.x*v1.x + wv.y*v1.y + wv.z*v1.z + wv.w*v1.w;
        a2 += wv.x*v2.x + wv.y*v2.y + wv.z*v2.z + wv.w*v2.w;
        a3 += wv.x*v3.x + wv.y*v3.y + wv.z*v3.z + wv.w*v3.w;
    }
    a0 = warp_sum_all(a0); a1 = warp_sum_all(a1);
    a2 = warp_sum_all(a2); a3 = warp_sum_all(a3);
    __shared__ float red[8][4];
    int wid = threadIdx.x >> 5;
    if ((threadIdx.x & 31) == 0) { red[wid][0]=a0; red[wid][1]=a1; red[wid][2]=a2; red[wid][3]=a3; }
    __syncthreads();
    if (threadIdx.x < 4) {
        float s = 0.f;
        #pragma unroll
        for (int w8 = 0; w8 < 8; w8++) s += red[w8][threadIdx.x];
        if (bias) s += __ldg(bias + i);
        y[(size_t)threadIdx.x * N + i] = s;
    }
}
__global__ void __launch_bounds__(256) gemv_wo(const float* __restrict__ Wo) {
    gemv4_body(Wo, d_attn_out, d_y1, nullptr, NHID, NHID);
}
__global__ void __launch_bounds__(256) gemv_w2(const float* __restrict__ W2) {
    gemv4_body(W2, d_cbuf, d_y2, nullptr, MLPDIM, NHID);
}
__global__ void __launch_bounds__(256) gemv_ws(const float* __restrict__ Ws,
                                               const float* __restrict__ bias,
                                               float* __restrict__ out) {
    gemv4_body(Ws, d_ln2, out, bias, NHID, 2048);
}

// ---------------- fused W0/W1 + SiLU (float4 loads) ----------------
__global__ void __launch_bounds__(256) mlp_kernel(const float* __restrict__ W0,
                                                  const float* __restrict__ W1) {
    int i = blockIdx.x;
    const float4* w04 = (const float4*)(W0 + (size_t)i * NHID);
    const float4* w14 = (const float4*)(W1 + (size_t)i * NHID);
    const float4* x4  = (const float4*)d_ln1;
    float a[4] = {0,0,0,0}, g[4] = {0,0,0,0};
    for (int k = threadIdx.x; k < NHID/4; k += 256) {
        float4 v0 = __ldg(w04 + k), v1 = __ldg(w14 + k);
        #pragma unroll
        for (int b = 0; b < 4; b++) {
            float4 xv = __ldg(x4 + b * (NHID/4) + k);
            a[b] += v0.x*xv.x + v0.y*xv.y + v0.z*xv.z + v0.w*xv.w;
            g[b] += v1.x*xv.x + v1.y*xv.y + v1.z*xv.z + v1.w*xv.w;
        }
    }
    __shared__ float ra[8][4], rg[8][4];
    int wid = threadIdx.x >> 5;
    #pragma unroll
    for (int b = 0; b < 4; b++) { a[b] = warp_sum_all(a[b]); g[b] = warp_sum_all(g[b]); }
    if ((threadIdx.x & 31) == 0) {
        #pragma unroll
        for (int b = 0; b < 4; b++) { ra[wid][b] = a[b]; rg[wid][b] = g[b]; }
    }
    __syncthreads();
    if (threadIdx.x < 4) {
        float sa = 0.f, sg = 0.f;
        #pragma unroll
        for (int w = 0; w < 8; w++) { sa += ra[w][threadIdx.x]; sg += rg[w][threadIdx.x]; }
        float si = sg / (1.f + expf(-sg));
        d_cbuf[(size_t)threadIdx.x * MLPDIM + i] = sa * si;
    }
}

// ---------------- layernorm ----------------
template<int STAGE>
__global__ void __launch_bounds__(256) ln_kernel(const float* __restrict__ g,
                                                 const float* __restrict__ bb) {
    const float* x = (STAGE == 0 ? d_y1 : d_y2) + (size_t)blockIdx.x * NHID;
    float* y       = (STAGE == 0 ? d_ln1 : d_ln2) + (size_t)blockIdx.x * NHID;
    float s = 0.f, s2 = 0.f;
    for (int k = threadIdx.x; k < NHID; k += 256) { float v = x[k]; s += v; s2 += v*v; }
    s = warp_sum_all(s); s2 = warp_sum_all(s2);
    __shared__ float rs[8], rs2[8];
    int wid = threadIdx.x >> 5;
    if ((threadIdx.x & 31) == 0) { rs[wid] = s; rs2[wid] = s2; }
    __syncthreads();
    if (threadIdx.x == 0) {
        float t = 0, t2 = 0;
        for (int w = 0; w < 8; w++) { t += rs[w]; t2 += rs2[w]; }
        rs[0] = t; rs2[0] = t2;
    }
    __syncthreads();
    float mu  = rs[0] / (float)NHID;
    float var = rs2[0] / (float)NHID - mu * mu;
    float inv = rsqrtf(var + 1e-5f);
    for (int k = threadIdx.x; k < NHID; k += 256)
        y[k] = (x[k] - mu) * inv * __ldg(g + k) + __ldg(bb + k);
}

// ---------------- launch ----------------
extern "C" void kernel_launch(void* const* d_in, const int* in_sizes, int n_in,
                              void* d_out, int out_size) {
    const float* hidden = (const float*)d_in[0];
    const float* q      = (const float*)d_in[1];
    const float* Wk     = (const float*)d_in[2];
    const float* Wv     = (const float*)d_in[3];
    const float* Wo     = (const float*)d_in[4];
    const float* W0     = (const float*)d_in[5];
    const float* W1     = (const float*)d_in[6];
    const float* W2     = (const float*)d_in[7];
    const float* Ws     = (const float*)d_in[8];
    const float* bs     = (const float*)d_in[9];
    const float* ln_g   = (const float*)d_in[10];
    const float* ln_b   = (const float*)d_in[11];
    float* out = (float*)d_out;

    static bool attr_done = false;
    if (!attr_done) {
        cudaFuncSetAttribute(gemm_kv, cudaFuncAttributeMaxDynamicSharedMemorySize, GEMM_SMEM);
        attr_done = true;
    }

    cvt_all<<<65536, 256>>>(hidden, Wk, Wv);
    cs_kernel<<<512, 256>>>();
    gemm_kv<<<dim3(32, 64, 2), 128, GEMM_SMEM>>>();   // K and V GEMMs fused
    scores_kernel<<<32768, 256>>>(q);
    softmax_kernel<<<128, 256>>>();
    attnv_kernel<<<dim3(128, 8), 128>>>();
    attnv_reduce<<<64, 256>>>();
    gemv_wo<<<4096, 256>>>(Wo);
    ln_kernel<0><<<4, 256>>>(ln_g, ln_b);
    mlp_kernel<<<12288, 256>>>(W0, W1);
    gemv_w2<<<4096, 256>>>(W2);
    ln_kernel<1><<<4, 256>>>(ln_g, ln_b);
    gemv_ws<<<2048, 256>>>(Ws, bs, out);
}

// round 10
// speedup vs baseline: 1.0023x; 1.0023x over previous
#include <cuda_runtime.h>
#include <cuda_fp16.h>
#include <cstdint>
#include <math.h>

#define NB 4
#define NS 2048
#define NHID 4096
#define NH 32
#define ND 128
#define NTOK (NB*NS)
#define MLPDIM (3*NHID)

// ---------------- scratch ----------------
__device__ __half  d_X16 [(size_t)NTOK*NHID];
__device__ __half  d_Wk16[(size_t)NHID*NHID];
__device__ __half  d_Wv16[(size_t)NHID*NHID];
__device__ __half  d_K16 [(size_t)NTOK*NHID];
__device__ __half  d_V16 [(size_t)NTOK*NHID];
__device__ float2  d_cs  [NS*64];
__device__ float   d_scores[NB*NH*NS];
__device__ float   d_attn  [NB*NH*NS];
__device__ float   d_attnv_part[8][NB*NH*ND];
__device__ float   d_attn_out[NB*NHID];
__device__ float   d_y1 [NB*NHID];
__device__ float   d_ln1[NB*NHID];
__device__ float   d_cbuf[NB*MLPDIM];
__device__ float   d_y2 [NB*NHID];
__device__ float   d_ln2[NB*NHID];

// ---------------- helpers ----------------
__device__ __forceinline__ float warp_sum_all(float v) {
    #pragma unroll
    for (int o = 16; o > 0; o >>= 1) v += __shfl_xor_sync(0xffffffffu, v, o);
    return v;
}
__device__ __forceinline__ float warp_max_all(float v) {
    #pragma unroll
    for (int o = 16; o > 0; o >>= 1) v = fmaxf(v, __shfl_xor_sync(0xffffffffu, v, o));
    return v;
}
__device__ __forceinline__ uint32_t smem_u32(const void* p) {
    return (uint32_t)__cvta_generic_to_shared(p);
}

// ==================== HMMA GEMM (fused K+V): C = X * W^T ====================
// CTA 128x128, 4 warps (warp tile 64x64), BK=64, double-buffered smem,
// register-prefetch pipeline (coalesced L1/L2-cached LDG), ONE barrier/iter.
// blockIdx.z: 0 -> K16 (plain), 1 -> V16 (RoPE fused in epilogue).
#define BM 128
#define BN 128
#define BK 64
#define LDSH 72                           // halves per smem row (64 + 8 pad)
#define RPB (LDSH*2)                      // 144 bytes per row
#define TILE_H (BM*LDSH)                  // halves per tile (A or B)
#define BUF_H (2*TILE_H)                  // halves per buffer (A+B)
#define TILE_B (BM*RPB)                   // 18432 bytes per tile
#define GEMM_SMEM (2*2*TILE_B)            // 73728 bytes (2 buffers x (A+B))
#define KCH (NHID/BK)                     // 64 iterations

__global__ void __launch_bounds__(128, 2) gemm_kv() {
    extern __shared__ __half sm[];        // buf0{A,B}, buf1{A,B}

    const int z = blockIdx.z;
    const __half* __restrict__ Aptr = d_X16;
    const __half* __restrict__ Bptr = z ? d_Wv16 : d_Wk16;
    __half* __restrict__ Cptr       = z ? d_V16  : d_K16;

    const int t = threadIdx.x;
    const int lane = t & 31, w = t >> 5;
    const int wm = w >> 1, wn = w & 1;            // 2 x 2 warps, 64x64 each
    const int bm = blockIdx.y * BM, bn = blockIdx.x * BN;

    float acc[4][8][4];
    #pragma unroll
    for (int a = 0; a < 4; a++)
        #pragma unroll
        for (int b = 0; b < 8; b++)
            #pragma unroll
            for (int c = 0; c < 4; c++) acc[a][b][c] = 0.f;

    // ---- coalesced load geometry (R8 pattern): 8 threads/row, 16 rows/pass ----
    const int lrow = t >> 3, lch = t & 7;         // rows 0..15, chunks 0..7 (16B)
    const __half* Ag = Aptr + (size_t)(bm + lrow) * NHID + lch * 8;
    const __half* Bg = Bptr + (size_t)(bn + lrow) * NHID + lch * 8;
    __half* Asp = &sm[lrow * LDSH + lch * 8];
    __half* Bsp = &sm[TILE_H + lrow * LDSH + lch * 8];

    uint4 ra[8], rb[8];                           // staging registers (64 regs)

    #define LDG_TILE(it) do {                                                   \
        _Pragma("unroll")                                                       \
        for (int r_ = 0; r_ < 8; r_++) {                                        \
            ra[r_] = *(const uint4*)(Ag + (size_t)r_ * 16 * NHID + (it) * BK);  \
            rb[r_] = *(const uint4*)(Bg + (size_t)r_ * 16 * NHID + (it) * BK);  \
        }                                                                       \
    } while (0)

    #define STS_TILE(s) do {                                                    \
        _Pragma("unroll")                                                       \
        for (int r_ = 0; r_ < 8; r_++) {                                        \
            *(uint4*)(Asp + (s) * BUF_H + r_ * 16 * LDSH) = ra[r_];             \
            *(uint4*)(Bsp + (s) * BUF_H + r_ * 16 * LDSH) = rb[r_];             \
        }                                                                       \
    } while (0)

    // prologue: tile0 -> buf0; tile1 staged in regs
    LDG_TILE(0);
    STS_TILE(0);
    LDG_TILE(1);
    __syncthreads();

    // per-warp ldmatrix byte offsets (buffer-relative)
    const uint32_t sbase = smem_u32(sm);
    const uint32_t a_off = (wm * 64 + (lane & 15)) * RPB + ((lane >> 4) << 4);
    const uint32_t b_off = (uint32_t)TILE_B
                         + (wn * 64 + (lane & 7) + ((lane >> 4) << 3)) * RPB
                         + ((lane & 8) << 1);

    for (int it = 0; it < KCH; it++) {
        // publish tile it+1 (regs -> other buffer), prefetch tile it+2
        if (it + 1 < KCH) STS_TILE((it + 1) & 1);
        if (it + 2 < KCH) LDG_TILE(it + 2);

        const uint32_t bufb = sbase + (uint32_t)(it & 1) * (2 * TILE_B);
        #pragma unroll
        for (int kk = 0; kk < 4; kk++) {
            uint32_t af[4][4], bf[4][4];
            #pragma unroll
            for (int mi = 0; mi < 4; mi++) {
                uint32_t addr = bufb + a_off + mi * (16 * RPB) + kk * 32;
                asm volatile("ldmatrix.sync.aligned.m8n8.x4.shared.b16 {%0,%1,%2,%3}, [%4];"
                    : "=r"(af[mi][0]), "=r"(af[mi][1]), "=r"(af[mi][2]), "=r"(af[mi][3])
                    : "r"(addr));
            }
            #pragma unroll
            for (int nb = 0; nb < 4; nb++) {
                uint32_t addr = bufb + b_off + nb * (16 * RPB) + kk * 32;
                asm volatile("ldmatrix.sync.aligned.m8n8.x4.shared.b16 {%0,%1,%2,%3}, [%4];"
                    : "=r"(bf[nb][0]), "=r"(bf[nb][1]), "=r"(bf[nb][2]), "=r"(bf[nb][3])
                    : "r"(addr));
            }
            #pragma unroll
            for (int mi = 0; mi < 4; mi++)
                #pragma unroll
                for (int ni = 0; ni < 8; ni++) {
                    uint32_t b0 = bf[ni >> 1][(ni & 1) * 2];
                    uint32_t b1 = bf[ni >> 1][(ni & 1) * 2 + 1];
                    asm volatile(
                        "mma.sync.aligned.m16n8k16.row.col.f32.f16.f16.f32 "
                        "{%0,%1,%2,%3}, {%4,%5,%6,%7}, {%8,%9}, {%0,%1,%2,%3};"
                        : "+f"(acc[mi][ni][0]), "+f"(acc[mi][ni][1]),
                          "+f"(acc[mi][ni][2]), "+f"(acc[mi][ni][3])
                        : "r"(af[mi][0]), "r"(af[mi][1]), "r"(af[mi][2]), "r"(af[mi][3]),
                          "r"(b0), "r"(b1));
                }
        }
        __syncthreads();   // publishes STS(it+1); guards reuse of buffer read this iter
    }

    // ---- epilogue (RoPE fused for V) ----
    #pragma unroll
    for (int mi = 0; mi < 4; mi++) {
        int r0 = bm + wm * 64 + mi * 16 + (lane >> 2);
        int s0 = r0 & (NS - 1), s1 = (r0 + 8) & (NS - 1);
        #pragma unroll
        for (int ni = 0; ni < 8; ni++) {
            int cc = bn + wn * 64 + ni * 8 + ((lane & 3) << 1);
            float v0 = acc[mi][ni][0], v1 = acc[mi][ni][1];
            float v2 = acc[mi][ni][2], v3 = acc[mi][ni][3];
            if (z) {
                int j = (cc & 127) >> 1;
                float2 cs0 = d_cs[s0 * 64 + j];
                float2 cs1 = d_cs[s1 * 64 + j];
                float t0 = v0*cs0.x - v1*cs0.y;
                float t1 = v1*cs0.x + v0*cs0.y;
                float t2 = v2*cs1.x - v3*cs1.y;
                float t3 = v3*cs1.x + v2*cs1.y;
                v0 = t0; v1 = t1; v2 = t2; v3 = t3;
            }
            *(__half2*)(Cptr + (size_t)r0 * NHID + cc)       = __floats2half2_rn(v0, v1);
            *(__half2*)(Cptr + (size_t)(r0 + 8) * NHID + cc) = __floats2half2_rn(v2, v3);
        }
    }
}

// ---------------- fp32 -> fp16 conversion ----------------
__global__ void __launch_bounds__(256) cvt_all(const float* __restrict__ X,
                                               const float* __restrict__ Wk,
                                               const float* __restrict__ Wv) {
    int i = blockIdx.x * 256 + threadIdx.x;
    const float* src; __half* dst; int j;
    if (i < 8388608)        { src = X;  dst = d_X16;  j = i; }
    else if (i < 12582912)  { src = Wk; dst = d_Wk16; j = i - 8388608; }
    else                    { src = Wv; dst = d_Wv16; j = i - 12582912; }
    float4 v = *(const float4*)(src + (size_t)j * 4);
    __half2* o = (__half2*)(dst + (size_t)j * 4);
    o[0] = __floats2half2_rn(v.x, v.y);
    o[1] = __floats2half2_rn(v.z, v.w);
}

// ---------------- RoPE cos/sin table ----------------
__global__ void __launch_bounds__(256) cs_kernel() {
    int i = blockIdx.x * 256 + threadIdx.x;
    if (i >= NS * 64) return;
    int s = i >> 6, j = i & 63;
    float theta = powf(10000.f, -2.f * (float)j / 128.f);
    float sv, cv;
    sincosf((float)s * theta, &sv, &cv);
    d_cs[i] = make_float2(cv, sv);
}

// ---------------- scores[b,h,s] = (R_s^T q_h) . K[b,s,h,:] ----------------
__global__ void __launch_bounds__(256) scores_kernel(const float* __restrict__ q) {
    int task = blockIdx.x * 8 + (threadIdx.x >> 5);
    int lane = threadIdx.x & 31;
    int bs = task >> 5, h = task & 31;
    int s  = bs & (NS - 1);
    const __half* kp = d_K16 + (size_t)bs * NHID + h * ND + lane * 4;
    __half2 ka = *(const __half2*)kp;
    __half2 kb = *(const __half2*)(kp + 2);
    float2 cs0 = d_cs[s * 64 + lane * 2];
    float2 cs1 = d_cs[s * 64 + lane * 2 + 1];
    const float* qp = q + h * ND + lane * 4;
    float q0 = __ldg(qp), q1 = __ldg(qp+1), q2 = __ldg(qp+2), q3 = __ldg(qp+3);
    float sum = (q0*cs0.x + q1*cs0.y) * __low2float(ka)
              + (q1*cs0.x - q0*cs0.y) * __high2float(ka)
              + (q2*cs1.x + q3*cs1.y) * __low2float(kb)
              + (q3*cs1.x - q2*cs1.y) * __high2float(kb);
    sum = warp_sum_all(sum);
    if (lane == 0) {
        int b = bs >> 11;
        d_scores[((b * NH + h) << 11) + s] = sum;
    }
}

// ---------------- softmax over s ----------------
__global__ void __launch_bounds__(256) softmax_kernel() {
    int bh = blockIdx.x;
    const float* sc = d_scores + (size_t)bh * NS;
    float* at = d_attn + (size_t)bh * NS;
    float v[8]; float m = -1e30f;
    #pragma unroll
    for (int i = 0; i < 8; i++) { v[i] = sc[threadIdx.x + i*256]; m = fmaxf(m, v[i]); }
    m = warp_max_all(m);
    __shared__ float r[8];
    int wid = threadIdx.x >> 5;
    if ((threadIdx.x & 31) == 0) r[wid] = m;
    __syncthreads();
    if (threadIdx.x == 0) { float t = r[0]; for (int w = 1; w < 8; w++) t = fmaxf(t, r[w]); r[0] = t; }
    __syncthreads();
    m = r[0];
    float tot = 0.f;
    #pragma unroll
    for (int i = 0; i < 8; i++) { v[i] = expf(v[i] - m); tot += v[i]; }
    tot = warp_sum_all(tot);
    __syncthreads();
    if ((threadIdx.x & 31) == 0) r[wid] = tot;
    __syncthreads();
    if (threadIdx.x == 0) { float t = 0; for (int w = 0; w < 8; w++) t += r[w]; r[0] = t; }
    __syncthreads();
    float inv = 1.f / r[0];
    #pragma unroll
    for (int i = 0; i < 8; i++) at[threadIdx.x + i*256] = v[i] * inv;
}

// ---------------- attn @ V (split-K) ----------------
__global__ void __launch_bounds__(128) attnv_kernel() {
    int bh = blockIdx.x, ch = blockIdx.y;
    int b = bh >> 5, h = bh & 31;
    const float* at = d_attn + (size_t)bh * NS + ch * 256;
    const __half* vp = d_V16 + (size_t)(b * NS + ch * 256) * NHID + h * ND + threadIdx.x;
    float acc = 0.f;
    #pragma unroll 8
    for (int i = 0; i < 256; i++)
        acc += at[i] * __half2float(vp[(size_t)i * NHID]);
    d_attnv_part[ch][bh * ND + threadIdx.x] = acc;
}
__global__ void __launch_bounds__(256) attnv_reduce() {
    int i = blockIdx.x * 256 + threadIdx.x;
    float s = 0.f;
    #pragma unroll
    for (int c = 0; c < 8; c++) s += d_attnv_part[c][i];
    d_attn_out[i] = s;
}

// ---------------- 4-row GEMV (float4 weight loads) ----------------
__device__ __forceinline__ void gemv4_body(const float* __restrict__ W, const float* __restrict__ x,
                                           float* __restrict__ y, const float* __restrict__ bias,
                                           int K, int N) {
    int i = blockIdx.x;
    const float4* w4 = (const float4*)(W + (size_t)i * K);
    const float4* x4 = (const float4*)x;
    int K4 = K >> 2;
    float a0 = 0, a1 = 0, a2 = 0, a3 = 0;
    for (int k = threadIdx.x; k < K4; k += 256) {
        float4 wv = __ldg(w4 + k);
        float4 v0 = __ldg(x4 + k);
        float4 v1 = __ldg(x4 + K4 + k);
        float4 v2 = __ldg(x4 + 2*K4 + k);
        float4 v3 = __ldg(x4 + 3*K4 + k);
        a0 += wv.x*v0.x + wv.y*v0.y + wv.z*v0.z + wv.w*v0.w;
        a1 += wv.x*v1.x + wv.y*v1.y + wv.z*v1.z + wv.w*v1.w;
        a2 += wv.x*v2.x + wv.y*v2.y + wv.z*v2.z + wv.w*v2.w;
        a3 += wv.x*v3.x + wv.y*v3.y + wv.z*v3.z + wv.w*v3.w;
    }
    a0 = warp_sum_all(a0); a1 = warp_sum_all(a1);
    a2 = warp_sum_all(a2); a3 = warp_sum_all(a3);
    __shared__ float red[8][4];
    int wid = threadIdx.x >> 5;
    if ((threadIdx.x & 31) == 0) { red[wid][0]=a0; red[wid][1]=a1; red[wid][2]=a2; red[wid][3]=a3; }
    __syncthreads();
    if (threadIdx.x < 4) {
        float s = 0.f;
        #pragma unroll
        for (int w8 = 0; w8 < 8; w8++) s += red[w8][threadIdx.x];
        if (bias) s += __ldg(bias + i);
        y[(size_t)threadIdx.x * N + i] = s;
    }
}
__global__ void __launch_bounds__(256) gemv_wo(const float* __restrict__ Wo) {
    gemv4_body(Wo, d_attn_out, d_y1, nullptr, NHID, NHID);
}
__global__ void __launch_bounds__(256) gemv_w2(const float* __restrict__ W2) {
    gemv4_body(W2, d_cbuf, d_y2, nullptr, MLPDIM, NHID);
}
__global__ void __launch_bounds__(256) gemv_ws(const float* __restrict__ Ws,
                                               const float* __restrict__ bias,
                                               float* __restrict__ out) {
    gemv4_body(Ws, d_ln2, out, bias, NHID, 2048);
}

// ---------------- fused W0/W1 + SiLU (float4 loads) ----------------
__global__ void __launch_bounds__(256) mlp_kernel(const float* __restrict__ W0,
                                                  const float* __restrict__ W1) {
    int i = blockIdx.x;
    const float4* w04 = (const float4*)(W0 + (size_t)i * NHID);
    const float4* w14 = (const float4*)(W1 + (size_t)i * NHID);
    const float4* x4  = (const float4*)d_ln1;
    float a[4] = {0,0,0,0}, g[4] = {0,0,0,0};
    for (int k = threadIdx.x; k < NHID/4; k += 256) {
        float4 v0 = __ldg(w04 + k), v1 = __ldg(w14 + k);
        #pragma unroll
        for (int b = 0; b < 4; b++) {
            float4 xv = __ldg(x4 + b * (NHID/4) + k);
            a[b] += v0.x*xv.x + v0.y*xv.y + v0.z*xv.z + v0.w*xv.w;
            g[b] += v1.x*xv.x + v1.y*xv.y + v1.z*xv.z + v1.w*xv.w;
        }
    }
    __shared__ float ra[8][4], rg[8][4];
    int wid = threadIdx.x >> 5;
    #pragma unroll
    for (int b = 0; b < 4; b++) { a[b] = warp_sum_all(a[b]); g[b] = warp_sum_all(g[b]); }
    if ((threadIdx.x & 31) == 0) {
        #pragma unroll
        for (int b = 0; b < 4; b++) { ra[wid][b] = a[b]; rg[wid][b] = g[b]; }
    }
    __syncthreads();
    if (threadIdx.x < 4) {
        float sa = 0.f, sg = 0.f;
        #pragma unroll
        for (int w = 0; w < 8; w++) { sa += ra[w][threadIdx.x]; sg += rg[w][threadIdx.x]; }
        float si = sg / (1.f + expf(-sg));
        d_cbuf[(size_t)threadIdx.x * MLPDIM + i] = sa * si;
    }
}

// ---------------- layernorm ----------------
template<int STAGE>
__global__ void __launch_bounds__(256) ln_kernel(const float* __restrict__ g,
                                                 const float* __restrict__ bb) {
    const float* x = (STAGE == 0 ? d_y1 : d_y2) + (size_t)blockIdx.x * NHID;
    float* y       = (STAGE == 0 ? d_ln1 : d_ln2) + (size_t)blockIdx.x * NHID;
    float s = 0.f, s2 = 0.f;
    for (int k = threadIdx.x; k < NHID; k += 256) { float v = x[k]; s += v; s2 += v*v; }
    s = warp_sum_all(s); s2 = warp_sum_all(s2);
    __shared__ float rs[8], rs2[8];
    int wid = threadIdx.x >> 5;
    if ((threadIdx.x & 31) == 0) { rs[wid] = s; rs2[wid] = s2; }
    __syncthreads();
    if (threadIdx.x == 0) {
        float t = 0, t2 = 0;
        for (int w = 0; w < 8; w++) { t += rs[w]; t2 += rs2[w]; }
        rs[0] = t; rs2[0] = t2;
    }
    __syncthreads();
    float mu  = rs[0] / (float)NHID;
    float var = rs2[0] / (float)NHID - mu * mu;
    float inv = rsqrtf(var + 1e-5f);
    for (int k = threadIdx.x; k < NHID; k += 256)
        y[k] = (x[k] - mu) * inv * __ldg(g + k) + __ldg(bb + k);
}

// ---------------- launch ----------------
extern "C" void kernel_launch(void* const* d_in, const int* in_sizes, int n_in,
                              void* d_out, int out_size) {
    const float* hidden = (const float*)d_in[0];
    const float* q      = (const float*)d_in[1];
    const float* Wk     = (const float*)d_in[2];
    const float* Wv     = (const float*)d_in[3];
    const float* Wo     = (const float*)d_in[4];
    const float* W0     = (const float*)d_in[5];
    const float* W1     = (const float*)d_in[6];
    const float* W2     = (const float*)d_in[7];
    const float* Ws     = (const float*)d_in[8];
    const float* bs     = (const float*)d_in[9];
    const float* ln_g   = (const float*)d_in[10];
    const float* ln_b   = (const float*)d_in[11];
    float* out = (float*)d_out;

    static bool attr_done = false;
    if (!attr_done) {
        cudaFuncSetAttribute(gemm_kv, cudaFuncAttributeMaxDynamicSharedMemorySize, GEMM_SMEM);
        attr_done = true;
    }

    cvt_all<<<65536, 256>>>(hidden, Wk, Wv);
    cs_kernel<<<512, 256>>>();
    gemm_kv<<<dim3(32, 64, 2), 128, GEMM_SMEM>>>();   // K and V GEMMs fused
    scores_kernel<<<32768, 256>>>(q);
    softmax_kernel<<<128, 256>>>();
    attnv_kernel<<<dim3(128, 8), 128>>>();
    attnv_reduce<<<64, 256>>>();
    gemv_wo<<<4096, 256>>>(Wo);
    ln_kernel<0><<<4, 256>>>(ln_g, ln_b);
    mlp_kernel<<<12288, 256>>>(W0, W1);
    gemv_w2<<<4096, 256>>>(W2);
    ln_kernel<1><<<4, 256>>>(ln_g, ln_b);
    gemv_ws<<<2048, 256>>>(Ws, bs, out);
}

// round 11
// speedup vs baseline: 1.0411x; 1.0387x over previous
#include <cuda_runtime.h>
#include <cuda_fp16.h>
#include <cstdint>
#include <math.h>

#define NB 4
#define NS 2048
#define NHID 4096
#define NH 32
#define ND 128
#define NTOK (NB*NS)
#define MLPDIM (3*NHID)

// ---------------- scratch ----------------
__device__ __half  d_X16 [(size_t)NTOK*NHID];
__device__ __half  d_Wk16[(size_t)NHID*NHID];
__device__ __half  d_Wv16[(size_t)NHID*NHID];
__device__ __half  d_V16 [(size_t)NTOK*NHID];
__device__ float2  d_cs  [NS*64];
__device__ float   d_scores[NB*NH*NS];
__device__ float   d_attn  [NB*NH*NS];
__device__ float   d_attnv_part[8][NB*NH*ND];
__device__ float   d_attn_out[NB*NHID];
__device__ float   d_y1 [NB*NHID];
__device__ float   d_ln1[NB*NHID];
__device__ float   d_cbuf[NB*MLPDIM];
__device__ float   d_y2 [NB*NHID];
__device__ float   d_ln2[NB*NHID];

// ---------------- helpers ----------------
__device__ __forceinline__ float warp_sum_all(float v) {
    #pragma unroll
    for (int o = 16; o > 0; o >>= 1) v += __shfl_xor_sync(0xffffffffu, v, o);
    return v;
}
__device__ __forceinline__ float warp_max_all(float v) {
    #pragma unroll
    for (int o = 16; o > 0; o >>= 1) v = fmaxf(v, __shfl_xor_sync(0xffffffffu, v, o));
    return v;
}
__device__ __forceinline__ uint32_t smem_u32(const void* p) {
    return (uint32_t)__cvta_generic_to_shared(p);
}

// ==================== HMMA GEMM (fused K+V): C = X * W^T ====================
// CTA 128x128, 4 warps (warp tile 64x64), BK=64, R8 synchronous coalesced loop.
// blockIdx.z == 0: K path — scores fused into epilogue, K never written to gmem.
// blockIdx.z == 1: V path — RoPE fused, V16 written.
#define BM 128
#define BN 128
#define BK 64
#define LDSH 72                           // halves per smem row (64 + 8 pad)
#define RPB (LDSH*2)                      // 144 bytes per row
#define TILE_B (BM*RPB)                   // 18432 bytes per tile
#define KCH (NHID/BK)                     // 64 iterations

__global__ void __launch_bounds__(128, 2) gemm_kv(const float* __restrict__ qp) {
    __shared__ __half sm[2*BM*LDSH];      // A tile then B tile

    const int z = blockIdx.z;
    const __half* __restrict__ Aptr = d_X16;
    const __half* __restrict__ Bptr = z ? d_Wv16 : d_Wk16;

    const int t = threadIdx.x;
    const int lane = t & 31, w = t >> 5;
    const int wm = w >> 1, wn = w & 1;            // 2 x 2 warps, 64x64 each
    const int bm = blockIdx.y * BM, bn = blockIdx.x * BN;

    float acc[4][8][4];
    #pragma unroll
    for (int a = 0; a < 4; a++)
        #pragma unroll
        for (int b = 0; b < 8; b++)
            #pragma unroll
            for (int c = 0; c < 4; c++) acc[a][b][c] = 0.f;

    // ---- coalesced load geometry (R8 pattern): 8 threads/row, 16 rows/pass ----
    const int lrow = t >> 3, lch = t & 7;         // rows 0..15, chunks 0..7 (16B)
    const __half* Ag = Aptr + (size_t)(bm + lrow) * NHID + lch * 8;
    const __half* Bg = Bptr + (size_t)(bn + lrow) * NHID + lch * 8;
    __half* Asp = &sm[lrow * LDSH + lch * 8];
    __half* Bsp = &sm[BM * LDSH + lrow * LDSH + lch * 8];

    // per-warp ldmatrix byte offsets
    const uint32_t sbase = smem_u32(sm);
    const uint32_t a_off = (wm * 64 + (lane & 15)) * RPB + ((lane >> 4) << 4);
    const uint32_t b_off = (uint32_t)TILE_B
                         + (wn * 64 + (lane & 7) + ((lane >> 4) << 3)) * RPB
                         + ((lane & 8) << 1);

    for (int k0 = 0; k0 < NHID; k0 += BK) {
        // ---- synchronous coalesced fill ----
        #pragma unroll
        for (int r = 0; r < 8; r++) {
            *(float4*)(Asp + r * 16 * LDSH) = *(const float4*)(Ag + (size_t)r * 16 * NHID + k0);
            *(float4*)(Bsp + r * 16 * LDSH) = *(const float4*)(Bg + (size_t)r * 16 * NHID + k0);
        }
        __syncthreads();

        #pragma unroll
        for (int kk = 0; kk < 4; kk++) {
            uint32_t af[4][4], bf[4][4];
            #pragma unroll
            for (int mi = 0; mi < 4; mi++) {
                uint32_t addr = sbase + a_off + mi * (16 * RPB) + kk * 32;
                asm volatile("ldmatrix.sync.aligned.m8n8.x4.shared.b16 {%0,%1,%2,%3}, [%4];"
                    : "=r"(af[mi][0]), "=r"(af[mi][1]), "=r"(af[mi][2]), "=r"(af[mi][3])
                    : "r"(addr));
            }
            #pragma unroll
            for (int nb = 0; nb < 4; nb++) {
                uint32_t addr = sbase + b_off + nb * (16 * RPB) + kk * 32;
                asm volatile("ldmatrix.sync.aligned.m8n8.x4.shared.b16 {%0,%1,%2,%3}, [%4];"
                    : "=r"(bf[nb][0]), "=r"(bf[nb][1]), "=r"(bf[nb][2]), "=r"(bf[nb][3])
                    : "r"(addr));
            }
            #pragma unroll
            for (int mi = 0; mi < 4; mi++)
                #pragma unroll
                for (int ni = 0; ni < 8; ni++) {
                    uint32_t b0 = bf[ni >> 1][(ni & 1) * 2];
                    uint32_t b1 = bf[ni >> 1][(ni & 1) * 2 + 1];
                    asm volatile(
                        "mma.sync.aligned.m16n8k16.row.col.f32.f16.f16.f32 "
                        "{%0,%1,%2,%3}, {%4,%5,%6,%7}, {%8,%9}, {%0,%1,%2,%3};"
                        : "+f"(acc[mi][ni][0]), "+f"(acc[mi][ni][1]),
                          "+f"(acc[mi][ni][2]), "+f"(acc[mi][ni][3])
                        : "r"(af[mi][0]), "r"(af[mi][1]), "r"(af[mi][2]), "r"(af[mi][3]),
                          "r"(b0), "r"(b1));
                }
        }
        __syncthreads();
    }

    if (z == 0) {
        // ---- K path: fused scores epilogue, no K materialization ----
        // CTA column block = one head (BN == ND). scores[b,h,s] = sum_d qrot(s,h,d) * K(r,d)
        const int h = blockIdx.x;
        float qv0[8], qv1[8];
        #pragma unroll
        for (int ni = 0; ni < 8; ni++) {
            int cc = wn * 64 + ni * 8 + ((lane & 3) << 1);   // head-local column (even)
            qv0[ni] = __ldg(qp + h * ND + cc);
            qv1[ni] = __ldg(qp + h * ND + cc + 1);
        }
        float scps[4][2];
        #pragma unroll
        for (int mi = 0; mi < 4; mi++) {
            int r0 = bm + wm * 64 + mi * 16 + (lane >> 2);
            int s0 = r0 & (NS - 1), s1 = (r0 + 8) & (NS - 1);
            float sc0 = 0.f, sc1 = 0.f;
            #pragma unroll
            for (int ni = 0; ni < 8; ni++) {
                int j = (wn * 64 + ni * 8 + ((lane & 3) << 1)) >> 1;
                float2 c0 = d_cs[s0 * 64 + j];
                float2 c1 = d_cs[s1 * 64 + j];
                float q0 = qv0[ni], q1 = qv1[ni];
                sc0 += (q0*c0.x + q1*c0.y) * acc[mi][ni][0]
                     + (q1*c0.x - q0*c0.y) * acc[mi][ni][1];
                sc1 += (q0*c1.x + q1*c1.y) * acc[mi][ni][2]
                     + (q1*c1.x - q0*c1.y) * acc[mi][ni][3];
            }
            #pragma unroll
            for (int o = 1; o < 4; o <<= 1) {
                sc0 += __shfl_xor_sync(0xffffffffu, sc0, o);
                sc1 += __shfl_xor_sync(0xffffffffu, sc1, o);
            }
            scps[mi][0] = sc0; scps[mi][1] = sc1;
        }
        float* sred = (float*)sm;          // reuse tile smem (post-barrier)
        if (wn == 0 && (lane & 3) == 0) {
            #pragma unroll
            for (int mi = 0; mi < 4; mi++) {
                int lr = wm * 64 + mi * 16 + (lane >> 2);
                sred[lr] = scps[mi][0];
                sred[lr + 8] = scps[mi][1];
            }
        }
        __syncthreads();
        if (wn == 1 && (lane & 3) == 0) {
            #pragma unroll
            for (int mi = 0; mi < 4; mi++) {
                int lr = wm * 64 + mi * 16 + (lane >> 2);
                int r0 = bm + lr;
                int b0 = r0 >> 11, s0 = r0 & (NS - 1);
                int r1 = r0 + 8;
                int b1 = r1 >> 11, s1 = r1 & (NS - 1);
                d_scores[((b0 * NH + h) << 11) + s0] = sred[lr] + scps[mi][0];
                d_scores[((b1 * NH + h) << 11) + s1] = sred[lr + 8] + scps[mi][1];
            }
        }
    } else {
        // ---- V path: RoPE fused, write V16 ----
        #pragma unroll
        for (int mi = 0; mi < 4; mi++) {
            int r0 = bm + wm * 64 + mi * 16 + (lane >> 2);
            int s0 = r0 & (NS - 1), s1 = (r0 + 8) & (NS - 1);
            #pragma unroll
            for (int ni = 0; ni < 8; ni++) {
                int cc = bn + wn * 64 + ni * 8 + ((lane & 3) << 1);
                int j = (cc & 127) >> 1;
                float2 cs0 = d_cs[s0 * 64 + j];
                float2 cs1 = d_cs[s1 * 64 + j];
                float v0 = acc[mi][ni][0], v1 = acc[mi][ni][1];
                float v2 = acc[mi][ni][2], v3 = acc[mi][ni][3];
                float t0 = v0*cs0.x - v1*cs0.y;
                float t1 = v1*cs0.x + v0*cs0.y;
                float t2 = v2*cs1.x - v3*cs1.y;
                float t3 = v3*cs1.x + v2*cs1.y;
                *(__half2*)(d_V16 + (size_t)r0 * NHID + cc)       = __floats2half2_rn(t0, t1);
                *(__half2*)(d_V16 + (size_t)(r0 + 8) * NHID + cc) = __floats2half2_rn(t2, t3);
            }
        }
    }
}

// ---------------- fp32 -> fp16 conversion ----------------
__global__ void __launch_bounds__(256) cvt_all(const float* __restrict__ X,
                                               const float* __restrict__ Wk,
                                               const float* __restrict__ Wv) {
    int i = blockIdx.x * 256 + threadIdx.x;
    const float* src; __half* dst; int j;
    if (i < 8388608)        { src = X;  dst = d_X16;  j = i; }
    else if (i < 12582912)  { src = Wk; dst = d_Wk16; j = i - 8388608; }
    else                    { src = Wv; dst = d_Wv16; j = i - 12582912; }
    float4 v = *(const float4*)(src + (size_t)j * 4);
    __half2* o = (__half2*)(dst + (size_t)j * 4);
    o[0] = __floats2half2_rn(v.x, v.y);
    o[1] = __floats2half2_rn(v.z, v.w);
}

// ---------------- RoPE cos/sin table ----------------
__global__ void __launch_bounds__(256) cs_kernel() {
    int i = blockIdx.x * 256 + threadIdx.x;
    if (i >= NS * 64) return;
    int s = i >> 6, j = i & 63;
    float theta = powf(10000.f, -2.f * (float)j / 128.f);
    float sv, cv;
    sincosf((float)s * theta, &sv, &cv);
    d_cs[i] = make_float2(cv, sv);
}

// ---------------- softmax over s ----------------
__global__ void __launch_bounds__(256) softmax_kernel() {
    int bh = blockIdx.x;
    const float* sc = d_scores + (size_t)bh * NS;
    float* at = d_attn + (size_t)bh * NS;
    float v[8]; float m = -1e30f;
    #pragma unroll
    for (int i = 0; i < 8; i++) { v[i] = sc[threadIdx.x + i*256]; m = fmaxf(m, v[i]); }
    m = warp_max_all(m);
    __shared__ float r[8];
    int wid = threadIdx.x >> 5;
    if ((threadIdx.x & 31) == 0) r[wid] = m;
    __syncthreads();
    if (threadIdx.x == 0) { float t = r[0]; for (int w = 1; w < 8; w++) t = fmaxf(t, r[w]); r[0] = t; }
    __syncthreads();
    m = r[0];
    float tot = 0.f;
    #pragma unroll
    for (int i = 0; i < 8; i++) { v[i] = expf(v[i] - m); tot += v[i]; }
    tot = warp_sum_all(tot);
    __syncthreads();
    if ((threadIdx.x & 31) == 0) r[wid] = tot;
    __syncthreads();
    if (threadIdx.x == 0) { float t = 0; for (int w = 0; w < 8; w++) t += r[w]; r[0] = t; }
    __syncthreads();
    float inv = 1.f / r[0];
    #pragma unroll
    for (int i = 0; i < 8; i++) at[threadIdx.x + i*256] = v[i] * inv;
}

// ---------------- attn @ V (split-K) ----------------
__global__ void __launch_bounds__(128) attnv_kernel() {
    int bh = blockIdx.x, ch = blockIdx.y;
    int b = bh >> 5, h = bh & 31;
    const float* at = d_attn + (size_t)bh * NS + ch * 256;
    const __half* vp = d_V16 + (size_t)(b * NS + ch * 256) * NHID + h * ND + threadIdx.x;
    float acc = 0.f;
    #pragma unroll 8
    for (int i = 0; i < 256; i++)
        acc += at[i] * __half2float(vp[(size_t)i * NHID]);
    d_attnv_part[ch][bh * ND + threadIdx.x] = acc;
}
__global__ void __launch_bounds__(256) attnv_reduce() {
    int i = blockIdx.x * 256 + threadIdx.x;
    float s = 0.f;
    #pragma unroll
    for (int c = 0; c < 8; c++) s += d_attnv_part[c][i];
    d_attn_out[i] = s;
}

// ---------------- 4-row GEMV (float4 weight loads) ----------------
template<int K4I>
__device__ __forceinline__ void gemv4_body(const float* __restrict__ W, const float* __restrict__ x,
                                           float* __restrict__ y, const float* __restrict__ bias,
                                           int K, int N) {
    int i = blockIdx.x;
    const float4* w4 = (const float4*)(W + (size_t)i * K);
    const float4* x4 = (const float4*)x;
    const int K4 = K >> 2;
    float a0 = 0, a1 = 0, a2 = 0, a3 = 0;
    #pragma unroll
    for (int ii = 0; ii < K4I; ii++) {
        int k = threadIdx.x + ii * 256;
        float4 wv = __ldg(w4 + k);
        float4 v0 = __ldg(x4 + k);
        float4 v1 = __ldg(x4 + K4 + k);
        float4 v2 = __ldg(x4 + 2*K4 + k);
        float4 v3 = __ldg(x4 + 3*K4 + k);
        a0 += wv.x*v0.x + wv.y*v0.y + wv.z*v0.z + wv.w*v0.w;
        a1 += wv.x*v1.x + wv.y*v1.y + wv.z*v1.z + wv.w*v1.w;
        a2 += wv.x*v2.x + wv.y*v2.y + wv.z*v2.z + wv.w*v2.w;
        a3 += wv.x*v3.x + wv.y*v3.y + wv.z*v3.z + wv.w*v3.w;
    }
    a0 = warp_sum_all(a0); a1 = warp_sum_all(a1);
    a2 = warp_sum_all(a2); a3 = warp_sum_all(a3);
    __shared__ float red[8][4];
    int wid = threadIdx.x >> 5;
    if ((threadIdx.x & 31) == 0) { red[wid][0]=a0; red[wid][1]=a1; red[wid][2]=a2; red[wid][3]=a3; }
    __syncthreads();
    if (threadIdx.x < 4) {
        float s = 0.f;
        #pragma unroll
        for (int w8 = 0; w8 < 8; w8++) s += red[w8][threadIdx.x];
        if (bias) s += __ldg(bias + i);
        y[(size_t)threadIdx.x * N + i] = s;
    }
}
__global__ void __launch_bounds__(256) gemv_wo(const float* __restrict__ Wo) {
    gemv4_body<4>(Wo, d_attn_out, d_y1, nullptr, NHID, NHID);
}
__global__ void __launch_bounds__(256) gemv_w2(const float* __restrict__ W2) {
    gemv4_body<12>(W2, d_cbuf, d_y2, nullptr, MLPDIM, NHID);
}
__global__ void __launch_bounds__(256) gemv_ws(const float* __restrict__ Ws,
                                               const float* __restrict__ bias,
                                               float* __restrict__ out) {
    gemv4_body<4>(Ws, d_ln2, out, bias, NHID, 2048);
}

// ---------------- fused W0/W1 + SiLU (float4 loads) ----------------
__global__ void __launch_bounds__(256) mlp_kernel(const float* __restrict__ W0,
                                                  const float* __restrict__ W1) {
    int i = blockIdx.x;
    const float4* w04 = (const float4*)(W0 + (size_t)i * NHID);
    const float4* w14 = (const float4*)(W1 + (size_t)i * NHID);
    const float4* x4  = (const float4*)d_ln1;
    float a[4] = {0,0,0,0}, g[4] = {0,0,0,0};
    #pragma unroll
    for (int ii = 0; ii < 4; ii++) {
        int k = threadIdx.x + ii * 256;
        float4 v0 = __ldg(w04 + k), v1 = __ldg(w14 + k);
        #pragma unroll
        for (int b = 0; b < 4; b++) {
            float4 xv = __ldg(x4 + b * (NHID/4) + k);
            a[b] += v0.x*xv.x + v0.y*xv.y + v0.z*xv.z + v0.w*xv.w;
            g[b] += v1.x*xv.x + v1.y*xv.y + v1.z*xv.z + v1.w*xv.w;
        }
    }
    __shared__ float ra[8][4], rg[8][4];
    int wid = threadIdx.x >> 5;
    #pragma unroll
    for (int b = 0; b < 4; b++) { a[b] = warp_sum_all(a[b]); g[b] = warp_sum_all(g[b]); }
    if ((threadIdx.x & 31) == 0) {
        #pragma unroll
        for (int b = 0; b < 4; b++) { ra[wid][b] = a[b]; rg[wid][b] = g[b]; }
    }
    __syncthreads();
    if (threadIdx.x < 4) {
        float sa = 0.f, sg = 0.f;
        #pragma unroll
        for (int w = 0; w < 8; w++) { sa += ra[w][threadIdx.x]; sg += rg[w][threadIdx.x]; }
        float si = sg / (1.f + expf(-sg));
        d_cbuf[(size_t)threadIdx.x * MLPDIM + i] = sa * si;
    }
}

// ---------------- layernorm ----------------
template<int STAGE>
__global__ void __launch_bounds__(256) ln_kernel(const float* __restrict__ g,
                                                 const float* __restrict__ bb) {
    const float* x = (STAGE == 0 ? d_y1 : d_y2) + (size_t)blockIdx.x * NHID;
    float* y       = (STAGE == 0 ? d_ln1 : d_ln2) + (size_t)blockIdx.x * NHID;
    float s = 0.f, s2 = 0.f;
    for (int k = threadIdx.x; k < NHID; k += 256) { float v = x[k]; s += v; s2 += v*v; }
    s = warp_sum_all(s); s2 = warp_sum_all(s2);
    __shared__ float rs[8], rs2[8];
    int wid = threadIdx.x >> 5;
    if ((threadIdx.x & 31) == 0) { rs[wid] = s; rs2[wid] = s2; }
    __syncthreads();
    if (threadIdx.x == 0) {
        float t = 0, t2 = 0;
        for (int w = 0; w < 8; w++) { t += rs[w]; t2 += rs2[w]; }
        rs[0] = t; rs2[0] = t2;
    }
    __syncthreads();
    float mu  = rs[0] / (float)NHID;
    float var = rs2[0] / (float)NHID - mu * mu;
    float inv = rsqrtf(var + 1e-5f);
    for (int k = threadIdx.x; k < NHID; k += 256)
        y[k] = (x[k] - mu) * inv * __ldg(g + k) + __ldg(bb + k);
}

// ---------------- launch ----------------
extern "C" void kernel_launch(void* const* d_in, const int* in_sizes, int n_in,
                              void* d_out, int out_size) {
    const float* hidden = (const float*)d_in[0];
    const float* q      = (const float*)d_in[1];
    const float* Wk     = (const float*)d_in[2];
    const float* Wv     = (const float*)d_in[3];
    const float* Wo     = (const float*)d_in[4];
    const float* W0     = (const float*)d_in[5];
    const float* W1     = (const float*)d_in[6];
    const float* W2     = (const float*)d_in[7];
    const float* Ws     = (const float*)d_in[8];
    const float* bs     = (const float*)d_in[9];
    const float* ln_g   = (const float*)d_in[10];
    const float* ln_b   = (const float*)d_in[11];
    float* out = (float*)d_out;

    cvt_all<<<65536, 256>>>(hidden, Wk, Wv);
    cs_kernel<<<512, 256>>>();
    gemm_kv<<<dim3(32, 64, 2), 128>>>(q);         // K(+scores) and V fused
    softmax_kernel<<<128, 256>>>();
    attnv_kernel<<<dim3(128, 8), 128>>>();
    attnv_reduce<<<64, 256>>>();
    gemv_wo<<<4096, 256>>>(Wo);
    ln_kernel<0><<<4, 256>>>(ln_g, ln_b);
    mlp_kernel<<<12288, 256>>>(W0, W1);
    gemv_w2<<<4096, 256>>>(W2);
    ln_kernel<1><<<4, 256>>>(ln_g, ln_b);
    gemv_ws<<<2048, 256>>>(Ws, bs, out);
}

// round 12
// speedup vs baseline: 1.0635x; 1.0215x over previous
#include <cuda_runtime.h>
#include <cuda_fp16.h>
#include <cstdint>
#include <math.h>

#define NB 4
#define NS 2048
#define NHID 4096
#define NH 32
#define ND 128
#define NTOK (NB*NS)
#define MLPDIM (3*NHID)

// ---------------- scratch ----------------
__device__ __half  d_X16 [(size_t)NTOK*NHID];
__device__ __half  d_Wk16[(size_t)NHID*NHID];
__device__ __half  d_Wv16[(size_t)NHID*NHID];
__device__ float2  d_cs  [NS*64];
__device__ float   d_scores[NB*NH*NS];
__device__ float   d_attn  [NB*NH*NS];
__device__ float   d_attnv_part[16][NB*NH*ND];
__device__ float   d_attn_out[NB*NHID];
__device__ float   d_y1 [NB*NHID];
__device__ float   d_ln1[NB*NHID];
__device__ float   d_cbuf[NB*MLPDIM];
__device__ float   d_y2 [NB*NHID];
__device__ float   d_ln2[NB*NHID];

// ---------------- helpers ----------------
__device__ __forceinline__ float warp_sum_all(float v) {
    #pragma unroll
    for (int o = 16; o > 0; o >>= 1) v += __shfl_xor_sync(0xffffffffu, v, o);
    return v;
}
__device__ __forceinline__ float warp_max_all(float v) {
    #pragma unroll
    for (int o = 16; o > 0; o >>= 1) v = fmaxf(v, __shfl_xor_sync(0xffffffffu, v, o));
    return v;
}
__device__ __forceinline__ uint32_t smem_u32(const void* p) {
    return (uint32_t)__cvta_generic_to_shared(p);
}

// ==================== HMMA GEMM: C = X * W^T (R8 mainloop) ====================
// CTA 128x128, 4 warps (warp tile 64x64), BK=64, synchronous coalesced loop.
// MODE 0: W=Wk, epilogue computes scores (K never materialized).
// MODE 1: W=Wv, epilogue applies RoPE and reduces attn @ V partials
//         (V never materialized). Requires d_attn ready.
#define BM 128
#define BN 128
#define BK 64
#define LDSH 72                           // halves per smem row (64 + 8 pad)
#define RPB (LDSH*2)                      // 144 bytes per row
#define TILE_B (BM*RPB)                   // 18432 bytes per tile
#define KCH (NHID/BK)                     // 64 iterations

template<int MODE>
__global__ void __launch_bounds__(128, 2) gemm_kv(const float* __restrict__ qp) {
    __shared__ __half sm[2*BM*LDSH];      // A tile then B tile

    const __half* __restrict__ Aptr = d_X16;
    const __half* __restrict__ Bptr = MODE ? d_Wv16 : d_Wk16;

    const int t = threadIdx.x;
    const int lane = t & 31, w = t >> 5;
    const int wm = w >> 1, wn = w & 1;            // 2 x 2 warps, 64x64 each
    const int bm = blockIdx.y * BM, bn = blockIdx.x * BN;

    float acc[4][8][4];
    #pragma unroll
    for (int a = 0; a < 4; a++)
        #pragma unroll
        for (int b = 0; b < 8; b++)
            #pragma unroll
            for (int c = 0; c < 4; c++) acc[a][b][c] = 0.f;

    // ---- coalesced load geometry: 8 threads/row, 16 rows/pass ----
    const int lrow = t >> 3, lch = t & 7;
    const __half* Ag = Aptr + (size_t)(bm + lrow) * NHID + lch * 8;
    const __half* Bg = Bptr + (size_t)(bn + lrow) * NHID + lch * 8;
    __half* Asp = &sm[lrow * LDSH + lch * 8];
    __half* Bsp = &sm[BM * LDSH + lrow * LDSH + lch * 8];

    const uint32_t sbase = smem_u32(sm);
    const uint32_t a_off = (wm * 64 + (lane & 15)) * RPB + ((lane >> 4) << 4);
    const uint32_t b_off = (uint32_t)TILE_B
                         + (wn * 64 + (lane & 7) + ((lane >> 4) << 3)) * RPB
                         + ((lane & 8) << 1);

    for (int k0 = 0; k0 < NHID; k0 += BK) {
        #pragma unroll
        for (int r = 0; r < 8; r++) {
            *(float4*)(Asp + r * 16 * LDSH) = *(const float4*)(Ag + (size_t)r * 16 * NHID + k0);
            *(float4*)(Bsp + r * 16 * LDSH) = *(const float4*)(Bg + (size_t)r * 16 * NHID + k0);
        }
        __syncthreads();

        #pragma unroll
        for (int kk = 0; kk < 4; kk++) {
            uint32_t af[4][4], bf[4][4];
            #pragma unroll
            for (int mi = 0; mi < 4; mi++) {
                uint32_t addr = sbase + a_off + mi * (16 * RPB) + kk * 32;
                asm volatile("ldmatrix.sync.aligned.m8n8.x4.shared.b16 {%0,%1,%2,%3}, [%4];"
                    : "=r"(af[mi][0]), "=r"(af[mi][1]), "=r"(af[mi][2]), "=r"(af[mi][3])
                    : "r"(addr));
            }
            #pragma unroll
            for (int nb = 0; nb < 4; nb++) {
                uint32_t addr = sbase + b_off + nb * (16 * RPB) + kk * 32;
                asm volatile("ldmatrix.sync.aligned.m8n8.x4.shared.b16 {%0,%1,%2,%3}, [%4];"
                    : "=r"(bf[nb][0]), "=r"(bf[nb][1]), "=r"(bf[nb][2]), "=r"(bf[nb][3])
                    : "r"(addr));
            }
            #pragma unroll
            for (int mi = 0; mi < 4; mi++)
                #pragma unroll
                for (int ni = 0; ni < 8; ni++) {
                    uint32_t b0 = bf[ni >> 1][(ni & 1) * 2];
                    uint32_t b1 = bf[ni >> 1][(ni & 1) * 2 + 1];
                    asm volatile(
                        "mma.sync.aligned.m16n8k16.row.col.f32.f16.f16.f32 "
                        "{%0,%1,%2,%3}, {%4,%5,%6,%7}, {%8,%9}, {%0,%1,%2,%3};"
                        : "+f"(acc[mi][ni][0]), "+f"(acc[mi][ni][1]),
                          "+f"(acc[mi][ni][2]), "+f"(acc[mi][ni][3])
                        : "r"(af[mi][0]), "r"(af[mi][1]), "r"(af[mi][2]), "r"(af[mi][3]),
                          "r"(b0), "r"(b1));
                }
        }
        __syncthreads();
    }

    const int h = blockIdx.x;             // column block == one head

    if (MODE == 0) {
        // ---- scores epilogue: scores[b,h,s] = sum_d qrot(s,d) * K(s,d) ----
        float qv0[8], qv1[8];
        #pragma unroll
        for (int ni = 0; ni < 8; ni++) {
            int cc = wn * 64 + ni * 8 + ((lane & 3) << 1);
            qv0[ni] = __ldg(qp + h * ND + cc);
            qv1[ni] = __ldg(qp + h * ND + cc + 1);
        }
        float scps[4][2];
        #pragma unroll
        for (int mi = 0; mi < 4; mi++) {
            int r0 = bm + wm * 64 + mi * 16 + (lane >> 2);
            int s0 = r0 & (NS - 1), s1 = (r0 + 8) & (NS - 1);
            float sc0 = 0.f, sc1 = 0.f;
            #pragma unroll
            for (int ni = 0; ni < 8; ni++) {
                int j = (wn * 64 + ni * 8 + ((lane & 3) << 1)) >> 1;
                float2 c0 = d_cs[s0 * 64 + j];
                float2 c1 = d_cs[s1 * 64 + j];
                float q0 = qv0[ni], q1 = qv1[ni];
                sc0 += (q0*c0.x + q1*c0.y) * acc[mi][ni][0]
                     + (q1*c0.x - q0*c0.y) * acc[mi][ni][1];
                sc1 += (q0*c1.x + q1*c1.y) * acc[mi][ni][2]
                     + (q1*c1.x - q0*c1.y) * acc[mi][ni][3];
            }
            #pragma unroll
            for (int o = 1; o < 4; o <<= 1) {
                sc0 += __shfl_xor_sync(0xffffffffu, sc0, o);
                sc1 += __shfl_xor_sync(0xffffffffu, sc1, o);
            }
            scps[mi][0] = sc0; scps[mi][1] = sc1;
        }
        float* sred = (float*)sm;
        if (wn == 0 && (lane & 3) == 0) {
            #pragma unroll
            for (int mi = 0; mi < 4; mi++) {
                int lr = wm * 64 + mi * 16 + (lane >> 2);
                sred[lr] = scps[mi][0];
                sred[lr + 8] = scps[mi][1];
            }
        }
        __syncthreads();
        if (wn == 1 && (lane & 3) == 0) {
            #pragma unroll
            for (int mi = 0; mi < 4; mi++) {
                int lr = wm * 64 + mi * 16 + (lane >> 2);
                int r0 = bm + lr;
                int b0 = r0 >> 11, s0 = r0 & (NS - 1);
                int r1 = r0 + 8;
                int b1 = r1 >> 11, s1 = r1 & (NS - 1);
                d_scores[((b0 * NH + h) << 11) + s0] = sred[lr] + scps[mi][0];
                d_scores[((b1 * NH + h) << 11) + s1] = sred[lr + 8] + scps[mi][1];
            }
        }
    } else {
        // ---- attn@V epilogue: partial[d] = sum_{s in tile} attn[b,h,s]*Vrope(s,d) ----
        const int b = bm >> 11;            // batch (tile never crosses boundary)
        const float* ap = d_attn + ((size_t)(b * NH + h) << 11);
        float po[16];
        #pragma unroll
        for (int i = 0; i < 16; i++) po[i] = 0.f;

        #pragma unroll
        for (int mi = 0; mi < 4; mi++) {
            int r0 = bm + wm * 64 + mi * 16 + (lane >> 2);
            int s0 = r0 & (NS - 1), s1 = (r0 + 8) & (NS - 1);
            float a0 = __ldg(ap + s0);
            float a1 = __ldg(ap + s1);
            #pragma unroll
            for (int ni = 0; ni < 8; ni++) {
                int j = (wn * 64 + ni * 8 + ((lane & 3) << 1)) >> 1;
                float2 c0 = d_cs[s0 * 64 + j];
                float2 c1 = d_cs[s1 * 64 + j];
                float v0 = acc[mi][ni][0], v1 = acc[mi][ni][1];
                float v2 = acc[mi][ni][2], v3 = acc[mi][ni][3];
                float t0 = v0*c0.x - v1*c0.y;
                float t1 = v1*c0.x + v0*c0.y;
                float t2 = v2*c1.x - v3*c1.y;
                float t3 = v3*c1.x + v2*c1.y;
                po[ni*2]     += a0*t0 + a1*t2;
                po[ni*2 + 1] += a0*t1 + a1*t3;
            }
        }
        // reduce over the 8 row-groups in the warp (lane bits 2..4)
        #pragma unroll
        for (int i = 0; i < 16; i++) {
            #pragma unroll
            for (int o = 4; o < 32; o <<= 1)
                po[i] += __shfl_xor_sync(0xffffffffu, po[i], o);
        }
        // combine the two wm warps through smem (reuses tile smem post-barrier)
        float* sred = (float*)sm;          // 128 floats
        if (wm == 0 && lane < 4) {
            #pragma unroll
            for (int ni = 0; ni < 8; ni++) {
                int cc = wn * 64 + ni * 8 + (lane << 1);
                sred[cc] = po[ni*2];
                sred[cc + 1] = po[ni*2 + 1];
            }
        }
        __syncthreads();
        if (wm == 1 && lane < 4) {
            int tile = blockIdx.y & 15;    // 16 tiles per batch
            float* outp = d_attnv_part[tile] + (size_t)(b * NH + h) * ND;
            #pragma unroll
            for (int ni = 0; ni < 8; ni++) {
                int cc = wn * 64 + ni * 8 + (lane << 1);
                outp[cc]     = sred[cc] + po[ni*2];
                outp[cc + 1] = sred[cc + 1] + po[ni*2 + 1];
            }
        }
    }
}

// ---------------- fp32 -> fp16 conversion ----------------
__global__ void __launch_bounds__(256) cvt_all(const float* __restrict__ X,
                                               const float* __restrict__ Wk,
                                               const float* __restrict__ Wv) {
    int i = blockIdx.x * 256 + threadIdx.x;
    const float* src; __half* dst; int j;
    if (i < 8388608)        { src = X;  dst = d_X16;  j = i; }
    else if (i < 12582912)  { src = Wk; dst = d_Wk16; j = i - 8388608; }
    else                    { src = Wv; dst = d_Wv16; j = i - 12582912; }
    float4 v = *(const float4*)(src + (size_t)j * 4);
    __half2* o = (__half2*)(dst + (size_t)j * 4);
    o[0] = __floats2half2_rn(v.x, v.y);
    o[1] = __floats2half2_rn(v.z, v.w);
}

// ---------------- RoPE cos/sin table ----------------
__global__ void __launch_bounds__(256) cs_kernel() {
    int i = blockIdx.x * 256 + threadIdx.x;
    if (i >= NS * 64) return;
    int s = i >> 6, j = i & 63;
    float theta = powf(10000.f, -2.f * (float)j / 128.f);
    float sv, cv;
    sincosf((float)s * theta, &sv, &cv);
    d_cs[i] = make_float2(cv, sv);
}

// ---------------- softmax over s ----------------
__global__ void __launch_bounds__(256) softmax_kernel() {
    int bh = blockIdx.x;
    const float* sc = d_scores + (size_t)bh * NS;
    float* at = d_attn + (size_t)bh * NS;
    float v[8]; float m = -1e30f;
    #pragma unroll
    for (int i = 0; i < 8; i++) { v[i] = sc[threadIdx.x + i*256]; m = fmaxf(m, v[i]); }
    m = warp_max_all(m);
    __shared__ float r[8];
    int wid = threadIdx.x >> 5;
    if ((threadIdx.x & 31) == 0) r[wid] = m;
    __syncthreads();
    if (threadIdx.x == 0) { float t = r[0]; for (int w = 1; w < 8; w++) t = fmaxf(t, r[w]); r[0] = t; }
    __syncthreads();
    m = r[0];
    float tot = 0.f;
    #pragma unroll
    for (int i = 0; i < 8; i++) { v[i] = expf(v[i] - m); tot += v[i]; }
    tot = warp_sum_all(tot);
    __syncthreads();
    if ((threadIdx.x & 31) == 0) r[wid] = tot;
    __syncthreads();
    if (threadIdx.x == 0) { float t = 0; for (int w = 0; w < 8; w++) t += r[w]; r[0] = t; }
    __syncthreads();
    float inv = 1.f / r[0];
    #pragma unroll
    for (int i = 0; i < 8; i++) at[threadIdx.x + i*256] = v[i] * inv;
}

// ---------------- attnv partial reduce (16 tiles) ----------------
__global__ void __launch_bounds__(256) attnv_reduce() {
    int i = blockIdx.x * 256 + threadIdx.x;   // (b*32+h)*128+d == b*4096 + h*128 + d
    float s = 0.f;
    #pragma unroll
    for (int c = 0; c < 16; c++) s += d_attnv_part[c][i];
    d_attn_out[i] = s;
}

// ---------------- 4-row GEMV (float4 weight loads) ----------------
template<int K4I>
__device__ __forceinline__ void gemv4_body(const float* __restrict__ W, const float* __restrict__ x,
                                           float* __restrict__ y, const float* __restrict__ bias,
                                           int K, int N) {
    int i = blockIdx.x;
    const float4* w4 = (const float4*)(W + (size_t)i * K);
    const float4* x4 = (const float4*)x;
    const int K4 = K >> 2;
    float a0 = 0, a1 = 0, a2 = 0, a3 = 0;
    #pragma unroll
    for (int ii = 0; ii < K4I; ii++) {
        int k = threadIdx.x + ii * 256;
        float4 wv = __ldg(w4 + k);
        float4 v0 = __ldg(x4 + k);
        float4 v1 = __ldg(x4 + K4 + k);
        float4 v2 = __ldg(x4 + 2*K4 + k);
        float4 v3 = __ldg(x4 + 3*K4 + k);
        a0 += wv.x*v0.x + wv.y*v0.y + wv.z*v0.z + wv.w*v0.w;
        a1 += wv.x*v1.x + wv.y*v1.y + wv.z*v1.z + wv.w*v1.w;
        a2 += wv.x*v2.x + wv.y*v2.y + wv.z*v2.z + wv.w*v2.w;
        a3 += wv.x*v3.x + wv.y*v3.y + wv.z*v3.z + wv.w*v3.w;
    }
    a0 = warp_sum_all(a0); a1 = warp_sum_all(a1);
    a2 = warp_sum_all(a2); a3 = warp_sum_all(a3);
    __shared__ float red[8][4];
    int wid = threadIdx.x >> 5;
    if ((threadIdx.x & 31) == 0) { red[wid][0]=a0; red[wid][1]=a1; red[wid][2]=a2; red[wid][3]=a3; }
    __syncthreads();
    if (threadIdx.x < 4) {
        float s = 0.f;
        #pragma unroll
        for (int w8 = 0; w8 < 8; w8++) s += red[w8][threadIdx.x];
        if (bias) s += __ldg(bias + i);
        y[(size_t)threadIdx.x * N + i] = s;
    }
}
__global__ void __launch_bounds__(256) gemv_wo(const float* __restrict__ Wo) {
    gemv4_body<4>(Wo, d_attn_out, d_y1, nullptr, NHID, NHID);
}
__global__ void __launch_bounds__(256) gemv_w2(const float* __restrict__ W2) {
    gemv4_body<12>(W2, d_cbuf, d_y2, nullptr, MLPDIM, NHID);
}
__global__ void __launch_bounds__(256) gemv_ws(const float* __restrict__ Ws,
                                               const float* __restrict__ bias,
                                               float* __restrict__ out) {
    gemv4_body<4>(Ws, d_ln2, out, bias, NHID, 2048);
}

// ---------------- fused W0/W1 + SiLU (float4 loads) ----------------
__global__ void __launch_bounds__(256) mlp_kernel(const float* __restrict__ W0,
                                                  const float* __restrict__ W1) {
    int i = blockIdx.x;
    const float4* w04 = (const float4*)(W0 + (size_t)i * NHID);
    const float4* w14 = (const float4*)(W1 + (size_t)i * NHID);
    const float4* x4  = (const float4*)d_ln1;
    float a[4] = {0,0,0,0}, g[4] = {0,0,0,0};
    #pragma unroll
    for (int ii = 0; ii < 4; ii++) {
        int k = threadIdx.x + ii * 256;
        float4 v0 = __ldg(w04 + k), v1 = __ldg(w14 + k);
        #pragma unroll
        for (int b = 0; b < 4; b++) {
            float4 xv = __ldg(x4 + b * (NHID/4) + k);
            a[b] += v0.x*xv.x + v0.y*xv.y + v0.z*xv.z + v0.w*xv.w;
            g[b] += v1.x*xv.x + v1.y*xv.y + v1.z*xv.z + v1.w*xv.w;
        }
    }
    __shared__ float ra[8][4], rg[8][4];
    int wid = threadIdx.x >> 5;
    #pragma unroll
    for (int b = 0; b < 4; b++) { a[b] = warp_sum_all(a[b]); g[b] = warp_sum_all(g[b]); }
    if ((threadIdx.x & 31) == 0) {
        #pragma unroll
        for (int b = 0; b < 4; b++) { ra[wid][b] = a[b]; rg[wid][b] = g[b]; }
    }
    __syncthreads();
    if (threadIdx.x < 4) {
        float sa = 0.f, sg = 0.f;
        #pragma unroll
        for (int w = 0; w < 8; w++) { sa += ra[w][threadIdx.x]; sg += rg[w][threadIdx.x]; }
        float si = sg / (1.f + expf(-sg));
        d_cbuf[(size_t)threadIdx.x * MLPDIM + i] = sa * si;
    }
}

// ---------------- layernorm ----------------
template<int STAGE>
__global__ void __launch_bounds__(256) ln_kernel(const float* __restrict__ g,
                                                 const float* __restrict__ bb) {
    const float* x = (STAGE == 0 ? d_y1 : d_y2) + (size_t)blockIdx.x * NHID;
    float* y       = (STAGE == 0 ? d_ln1 : d_ln2) + (size_t)blockIdx.x * NHID;
    float s = 0.f, s2 = 0.f;
    for (int k = threadIdx.x; k < NHID; k += 256) { float v = x[k]; s += v; s2 += v*v; }
    s = warp_sum_all(s); s2 = warp_sum_all(s2);
    __shared__ float rs[8], rs2[8];
    int wid = threadIdx.x >> 5;
    if ((threadIdx.x & 31) == 0) { rs[wid] = s; rs2[wid] = s2; }
    __syncthreads();
    if (threadIdx.x == 0) {
        float t = 0, t2 = 0;
        for (int w = 0; w < 8; w++) { t += rs[w]; t2 += rs2[w]; }
        rs[0] = t; rs2[0] = t2;
    }
    __syncthreads();
    float mu  = rs[0] / (float)NHID;
    float var = rs2[0] / (float)NHID - mu * mu;
    float inv = rsqrtf(var + 1e-5f);
    for (int k = threadIdx.x; k < NHID; k += 256)
        y[k] = (x[k] - mu) * inv * __ldg(g + k) + __ldg(bb + k);
}

// ---------------- launch ----------------
extern "C" void kernel_launch(void* const* d_in, const int* in_sizes, int n_in,
                              void* d_out, int out_size) {
    const float* hidden = (const float*)d_in[0];
    const float* q      = (const float*)d_in[1];
    const float* Wk     = (const float*)d_in[2];
    const float* Wv     = (const float*)d_in[3];
    const float* Wo     = (const float*)d_in[4];
    const float* W0     = (const float*)d_in[5];
    const float* W1     = (const float*)d_in[6];
    const float* W2     = (const float*)d_in[7];
    const float* Ws     = (const float*)d_in[8];
    const float* bs     = (const float*)d_in[9];
    const float* ln_g   = (const float*)d_in[10];
    const float* ln_b   = (const float*)d_in[11];
    float* out = (float*)d_out;

    cvt_all<<<65536, 256>>>(hidden, Wk, Wv);
    cs_kernel<<<512, 256>>>();
    gemm_kv<0><<<dim3(32, 64), 128>>>(q);         // K-GEMM + fused scores
    softmax_kernel<<<128, 256>>>();
    gemm_kv<1><<<dim3(32, 64), 128>>>(q);         // V-GEMM + fused RoPE + attn@V partials
    attnv_reduce<<<64, 256>>>();
    gemv_wo<<<4096, 256>>>(Wo);
    ln_kernel<0><<<4, 256>>>(ln_g, ln_b);
    mlp_kernel<<<12288, 256>>>(W0, W1);
    gemv_w2<<<4096, 256>>>(W2);
    ln_kernel<1><<<4, 256>>>(ln_g, ln_b);
    gemv_ws<<<2048, 256>>>(Ws, bs, out);
}

// round 13
// speedup vs baseline: 1.2859x; 1.2091x over previous
#include <cuda_runtime.h>
#include <cuda_fp16.h>
#include <cstdint>
#include <math.h>

#define NB 4
#define NS 2048
#define NHID 4096
#define NH 32
#define ND 128
#define NTOK (NB*NS)
#define MLPDIM (3*NHID)

// ---------------- scratch ----------------
__device__ __half  d_X16 [(size_t)NTOK*NHID];
__device__ __half  d_Wv16[(size_t)NHID*NHID];
__device__ __half  d_WkT [(size_t)NHID*NHID];        // [k][h*128+d]
__device__ __half  d_Qr  [(size_t)NH*NS*ND];         // [h][s][d] rotated q
__device__ __half  d_A   [(size_t)NH*NS*NHID];       // [h][s][k]  (512MB)
__device__ float2  d_cs  [NS*64];
__device__ float   d_scores[NB*NH*NS];
__device__ float   d_attn  [NB*NH*NS];
__device__ float   d_attnv_part[16][NB*NH*ND];
__device__ float   d_attn_out[NB*NHID];
__device__ float   d_y1 [NB*NHID];
__device__ float   d_ln1[NB*NHID];
__device__ float   d_cbuf[NB*MLPDIM];
__device__ float   d_y2 [NB*NHID];
__device__ float   d_ln2[NB*NHID];

// ---------------- helpers ----------------
__device__ __forceinline__ float warp_sum_all(float v) {
    #pragma unroll
    for (int o = 16; o > 0; o >>= 1) v += __shfl_xor_sync(0xffffffffu, v, o);
    return v;
}
__device__ __forceinline__ float warp_max_all(float v) {
    #pragma unroll
    for (int o = 16; o > 0; o >>= 1) v = fmaxf(v, __shfl_xor_sync(0xffffffffu, v, o));
    return v;
}
__device__ __forceinline__ uint32_t smem_u32(const void* p) {
    return (uint32_t)__cvta_generic_to_shared(p);
}

// ---------------- GEMM tile constants (champion config) ----------------
#define BM 128
#define BN 128
#define BK 64
#define LDSH 72
#define RPB (LDSH*2)
#define TILE_B (BM*RPB)

// ======== MMA mainloop macro (R8 champion: sync coalesced fill, 4 warps 64x64) ========
#define GEMM_MAINLOOP(KTOT)                                                              \
    for (int k0 = 0; k0 < (KTOT); k0 += BK) {                                            \
        _Pragma("unroll")                                                                \
        for (int r = 0; r < 8; r++) {                                                    \
            *(float4*)(Asp + r * 16 * LDSH) = *(const float4*)(Ag + (size_t)r * 16 * lda + k0); \
            *(float4*)(Bsp + r * 16 * LDSH) = *(const float4*)(Bg + (size_t)r * 16 * ldb + k0); \
        }                                                                                \
        __syncthreads();                                                                 \
        _Pragma("unroll")                                                                \
        for (int kk = 0; kk < 4; kk++) {                                                 \
            uint32_t af[4][4], bf[4][4];                                                 \
            _Pragma("unroll")                                                            \
            for (int mi = 0; mi < 4; mi++) {                                             \
                uint32_t addr = sbase + a_off + mi * (16 * RPB) + kk * 32;               \
                asm volatile("ldmatrix.sync.aligned.m8n8.x4.shared.b16 {%0,%1,%2,%3}, [%4];" \
                    : "=r"(af[mi][0]), "=r"(af[mi][1]), "=r"(af[mi][2]), "=r"(af[mi][3]) \
                    : "r"(addr));                                                        \
            }                                                                            \
            _Pragma("unroll")                                                            \
            for (int nb = 0; nb < 4; nb++) {                                             \
                uint32_t addr = sbase + b_off + nb * (16 * RPB) + kk * 32;               \
                asm volatile("ldmatrix.sync.aligned.m8n8.x4.shared.b16 {%0,%1,%2,%3}, [%4];" \
                    : "=r"(bf[nb][0]), "=r"(bf[nb][1]), "=r"(bf[nb][2]), "=r"(bf[nb][3]) \
                    : "r"(addr));                                                        \
            }                                                                            \
            _Pragma("unroll")                                                            \
            for (int mi = 0; mi < 4; mi++)                                               \
                _Pragma("unroll")                                                        \
                for (int ni = 0; ni < 8; ni++) {                                         \
                    uint32_t b0 = bf[ni >> 1][(ni & 1) * 2];                             \
                    uint32_t b1 = bf[ni >> 1][(ni & 1) * 2 + 1];                         \
                    asm volatile(                                                        \
                        "mma.sync.aligned.m16n8k16.row.col.f32.f16.f16.f32 "             \
                        "{%0,%1,%2,%3}, {%4,%5,%6,%7}, {%8,%9}, {%0,%1,%2,%3};"          \
                        : "+f"(acc[mi][ni][0]), "+f"(acc[mi][ni][1]),                    \
                          "+f"(acc[mi][ni][2]), "+f"(acc[mi][ni][3])                     \
                        : "r"(af[mi][0]), "r"(af[mi][1]), "r"(af[mi][2]), "r"(af[mi][3]),\
                          "r"(b0), "r"(b1));                                             \
                }                                                                        \
        }                                                                                \
        __syncthreads();                                                                 \
    }

#define GEMM_PRELUDE(APTR, LDA, BPTR, LDB)                                               \
    const int t = threadIdx.x;                                                           \
    const int lane = t & 31, w = t >> 5;                                                 \
    const int wm = w >> 1, wn = w & 1;                                                   \
    float acc[4][8][4];                                                                  \
    _Pragma("unroll")                                                                    \
    for (int a = 0; a < 4; a++)                                                          \
        _Pragma("unroll")                                                                \
        for (int b = 0; b < 8; b++)                                                      \
            _Pragma("unroll")                                                            \
            for (int c = 0; c < 4; c++) acc[a][b][c] = 0.f;                              \
    const int lrow = t >> 3, lch = t & 7;                                                \
    const int lda = (LDA), ldb = (LDB);                                                  \
    const __half* Ag = (APTR) + (size_t)lrow * lda + lch * 8;                            \
    const __half* Bg = (BPTR) + (size_t)lrow * ldb + lch * 8;                            \
    __half* Asp = &sm[lrow * LDSH + lch * 8];                                            \
    __half* Bsp = &sm[BM * LDSH + lrow * LDSH + lch * 8];                                \
    const uint32_t sbase = smem_u32(sm);                                                 \
    const uint32_t a_off = (wm * 64 + (lane & 15)) * RPB + ((lane >> 4) << 4);           \
    const uint32_t b_off = (uint32_t)TILE_B                                              \
                         + (wn * 64 + (lane & 7) + ((lane >> 4) << 3)) * RPB             \
                         + ((lane & 8) << 1)

// ==================== A-GEMM: A[h][s][k] = Qrot_h @ Wk_h (K'=128) ====================
__global__ void __launch_bounds__(128, 2) agemm() {
    __shared__ __half sm[2*BM*LDSH];
    const int h  = blockIdx.z;
    const int bm = blockIdx.y * BM;    // s tile
    const int bn = blockIdx.x * BN;    // k tile
    GEMM_PRELUDE(d_Qr + ((size_t)h * NS + bm) * ND,       ND,
                 d_WkT + (size_t)bn * NHID + h * ND,      NHID);
    GEMM_MAINLOOP(ND)

    // epilogue: store fp16 A
    __half* Abase = d_A + (size_t)h * NS * NHID;
    #pragma unroll
    for (int mi = 0; mi < 4; mi++) {
        int r0 = bm + wm * 64 + mi * 16 + (lane >> 2);
        #pragma unroll
        for (int ni = 0; ni < 8; ni++) {
            int cc = bn + wn * 64 + ni * 8 + ((lane & 3) << 1);
            *(__half2*)(Abase + (size_t)r0 * NHID + cc) =
                __floats2half2_rn(acc[mi][ni][0], acc[mi][ni][1]);
            *(__half2*)(Abase + (size_t)(r0 + 8) * NHID + cc) =
                __floats2half2_rn(acc[mi][ni][2], acc[mi][ni][3]);
        }
    }
}

// ==================== V-GEMM + fused RoPE + attn@V partials (R12) ====================
__global__ void __launch_bounds__(128, 2) gemm_v() {
    __shared__ __half sm[2*BM*LDSH];
    const int bm = blockIdx.y * BM, bn = blockIdx.x * BN;
    GEMM_PRELUDE(d_X16 + (size_t)bm * NHID, NHID,
                 d_Wv16 + (size_t)bn * NHID, NHID);
    GEMM_MAINLOOP(NHID)

    const int h = blockIdx.x;
    const int b = bm >> 11;
    const float* ap = d_attn + ((size_t)(b * NH + h) << 11);
    float po[16];
    #pragma unroll
    for (int i = 0; i < 16; i++) po[i] = 0.f;

    #pragma unroll
    for (int mi = 0; mi < 4; mi++) {
        int r0 = bm + wm * 64 + mi * 16 + (lane >> 2);
        int s0 = r0 & (NS - 1), s1 = (r0 + 8) & (NS - 1);
        float a0 = __ldg(ap + s0);
        float a1 = __ldg(ap + s1);
        #pragma unroll
        for (int ni = 0; ni < 8; ni++) {
            int j = (wn * 64 + ni * 8 + ((lane & 3) << 1)) >> 1;
            float2 c0 = d_cs[s0 * 64 + j];
            float2 c1 = d_cs[s1 * 64 + j];
            float v0 = acc[mi][ni][0], v1 = acc[mi][ni][1];
            float v2 = acc[mi][ni][2], v3 = acc[mi][ni][3];
            float t0 = v0*c0.x - v1*c0.y;
            float t1 = v1*c0.x + v0*c0.y;
            float t2 = v2*c1.x - v3*c1.y;
            float t3 = v3*c1.x + v2*c1.y;
            po[ni*2]     += a0*t0 + a1*t2;
            po[ni*2 + 1] += a0*t1 + a1*t3;
        }
    }
    #pragma unroll
    for (int i = 0; i < 16; i++) {
        #pragma unroll
        for (int o = 4; o < 32; o <<= 1)
            po[i] += __shfl_xor_sync(0xffffffffu, po[i], o);
    }
    float* sred = (float*)sm;
    if (wm == 0 && lane < 4) {
        #pragma unroll
        for (int ni = 0; ni < 8; ni++) {
            int cc = wn * 64 + ni * 8 + (lane << 1);
            sred[cc] = po[ni*2];
            sred[cc + 1] = po[ni*2 + 1];
        }
    }
    __syncthreads();
    if (wm == 1 && lane < 4) {
        int tile = blockIdx.y & 15;
        float* outp = d_attnv_part[tile] + (size_t)(b * NH + h) * ND;
        #pragma unroll
        for (int ni = 0; ni < 8; ni++) {
            int cc = wn * 64 + ni * 8 + (lane << 1);
            outp[cc]     = sred[cc] + po[ni*2];
            outp[cc + 1] = sred[cc + 1] + po[ni*2 + 1];
        }
    }
}

// ---------------- fp32 -> fp16 conversion (X, Wv) ----------------
__global__ void __launch_bounds__(256) cvt_all(const float* __restrict__ X,
                                               const float* __restrict__ Wv) {
    int i = blockIdx.x * 256 + threadIdx.x;
    const float* src; __half* dst; int j;
    if (i < 8388608) { src = X;  dst = d_X16;  j = i; }
    else             { src = Wv; dst = d_Wv16; j = i - 8388608; }
    float4 v = *(const float4*)(src + (size_t)j * 4);
    __half2* o = (__half2*)(dst + (size_t)j * 4);
    o[0] = __floats2half2_rn(v.x, v.y);
    o[1] = __floats2half2_rn(v.z, v.w);
}

// ---------------- Wk transpose + fp16: WkT[k][hd] ----------------
__global__ void __launch_bounds__(256) wkt_kernel(const float* __restrict__ Wk) {
    __shared__ float tile[32][33];
    int bx = blockIdx.x * 32, by = blockIdx.y * 32;   // bx: k, by: hd
    int tx = threadIdx.x & 31, ty = threadIdx.x >> 5; // 32 x 8
    #pragma unroll
    for (int i = 0; i < 32; i += 8)
        tile[ty + i][tx] = Wk[(size_t)(by + ty + i) * NHID + bx + tx];
    __syncthreads();
    #pragma unroll
    for (int i = 0; i < 32; i += 8)
        d_WkT[(size_t)(bx + ty + i) * NHID + by + tx] = __float2half(tile[tx][ty + i]);
}

// ---------------- RoPE cos/sin table ----------------
__global__ void __launch_bounds__(256) cs_kernel() {
    int i = blockIdx.x * 256 + threadIdx.x;
    if (i >= NS * 64) return;
    int s = i >> 6, j = i & 63;
    float theta = powf(10000.f, -2.f * (float)j / 128.f);
    float sv, cv;
    sincosf((float)s * theta, &sv, &cv);
    d_cs[i] = make_float2(cv, sv);
}

// ---------------- rotated query: Qr[h][s][d] fp16 ----------------
__global__ void __launch_bounds__(256) qrot_kernel(const float* __restrict__ qp) {
    int i = blockIdx.x * 256 + threadIdx.x;   // h*131072 + s*64 + j
    int h = i >> 17, rem = i & 131071;
    int s = rem >> 6, j = rem & 63;
    float q0 = __ldg(qp + h * ND + 2 * j);
    float q1 = __ldg(qp + h * ND + 2 * j + 1);
    float2 c = d_cs[s * 64 + j];
    ((__half2*)d_Qr)[((size_t)h * NS + s) * 64 + j] =
        __floats2half2_rn(q0 * c.x + q1 * c.y, q1 * c.x - q0 * c.y);
}

// ---------------- scores dot: S[b,h,s] = X16[b,s,:] . A[h,s,:] ----------------
__global__ void __launch_bounds__(256) scores_dot() {
    const int s = blockIdx.x;
    const int w = threadIdx.x >> 5, lane = threadIdx.x & 31;
    const int h0 = w * 4;
    float acc[4][4];
    #pragma unroll
    for (int i = 0; i < 4; i++)
        #pragma unroll
        for (int b = 0; b < 4; b++) acc[i][b] = 0.f;

    const __half* Abase = d_A + ((size_t)h0 * NS + s) * NHID;
    const __half* Xbase = d_X16 + (size_t)s * NHID;

    for (int ch = 0; ch < 16; ch++) {
        int k = ch * 256 + lane * 8;
        uint4 xv[4];
        #pragma unroll
        for (int b = 0; b < 4; b++)
            xv[b] = *(const uint4*)(Xbase + (size_t)b * NS * NHID + k);
        #pragma unroll
        for (int hi = 0; hi < 4; hi++) {
            uint4 av = *(const uint4*)(Abase + (size_t)hi * NS * NHID + k);
            const __half2* ah = (const __half2*)&av;
            #pragma unroll
            for (int b = 0; b < 4; b++) {
                const __half2* xh = (const __half2*)&xv[b];
                #pragma unroll
                for (int p = 0; p < 4; p++) {
                    float2 fa = __half22float2(ah[p]);
                    float2 fx = __half22float2(xh[p]);
                    acc[hi][b] += fa.x * fx.x + fa.y * fx.y;
                }
            }
        }
    }
    #pragma unroll
    for (int hi = 0; hi < 4; hi++)
        #pragma unroll
        for (int b = 0; b < 4; b++)
            acc[hi][b] = warp_sum_all(acc[hi][b]);
    if (lane == 0) {
        #pragma unroll
        for (int hi = 0; hi < 4; hi++)
            #pragma unroll
            for (int b = 0; b < 4; b++)
                d_scores[((b * NH + h0 + hi) << 11) + s] = acc[hi][b];
    }
}

// ---------------- softmax over s ----------------
__global__ void __launch_bounds__(256) softmax_kernel() {
    int bh = blockIdx.x;
    const float* sc = d_scores + (size_t)bh * NS;
    float* at = d_attn + (size_t)bh * NS;
    float v[8]; float m = -1e30f;
    #pragma unroll
    for (int i = 0; i < 8; i++) { v[i] = sc[threadIdx.x + i*256]; m = fmaxf(m, v[i]); }
    m = warp_max_all(m);
    __shared__ float r[8];
    int wid = threadIdx.x >> 5;
    if ((threadIdx.x & 31) == 0) r[wid] = m;
    __syncthreads();
    if (threadIdx.x == 0) { float t = r[0]; for (int w = 1; w < 8; w++) t = fmaxf(t, r[w]); r[0] = t; }
    __syncthreads();
    m = r[0];
    float tot = 0.f;
    #pragma unroll
    for (int i = 0; i < 8; i++) { v[i] = expf(v[i] - m); tot += v[i]; }
    tot = warp_sum_all(tot);
    __syncthreads();
    if ((threadIdx.x & 31) == 0) r[wid] = tot;
    __syncthreads();
    if (threadIdx.x == 0) { float t = 0; for (int w = 0; w < 8; w++) t += r[w]; r[0] = t; }
    __syncthreads();
    float inv = 1.f / r[0];
    #pragma unroll
    for (int i = 0; i < 8; i++) at[threadIdx.x + i*256] = v[i] * inv;
}

// ---------------- attnv partial reduce (16 tiles) ----------------
__global__ void __launch_bounds__(256) attnv_reduce() {
    int i = blockIdx.x * 256 + threadIdx.x;
    float s = 0.f;
    #pragma unroll
    for (int c = 0; c < 16; c++) s += d_attnv_part[c][i];
    d_attn_out[i] = s;
}

// ---------------- 4-row GEMV (float4 weight loads) ----------------
template<int K4I>
__device__ __forceinline__ void gemv4_body(const float* __restrict__ W, const float* __restrict__ x,
                                           float* __restrict__ y, const float* __restrict__ bias,
                                           int K, int N) {
    int i = blockIdx.x;
    const float4* w4 = (const float4*)(W + (size_t)i * K);
    const float4* x4 = (const float4*)x;
    const int K4 = K >> 2;
    float a0 = 0, a1 = 0, a2 = 0, a3 = 0;
    #pragma unroll
    for (int ii = 0; ii < K4I; ii++) {
        int k = threadIdx.x + ii * 256;
        float4 wv = __ldg(w4 + k);
        float4 v0 = __ldg(x4 + k);
        float4 v1 = __ldg(x4 + K4 + k);
        float4 v2 = __ldg(x4 + 2*K4 + k);
        float4 v3 = __ldg(x4 + 3*K4 + k);
        a0 += wv.x*v0.x + wv.y*v0.y + wv.z*v0.z + wv.w*v0.w;
        a1 += wv.x*v1.x + wv.y*v1.y + wv.z*v1.z + wv.w*v1.w;
        a2 += wv.x*v2.x + wv.y*v2.y + wv.z*v2.z + wv.w*v2.w;
        a3 += wv.x*v3.x + wv.y*v3.y + wv.z*v3.z + wv.w*v3.w;
    }
    a0 = warp_sum_all(a0); a1 = warp_sum_all(a1);
    a2 = warp_sum_all(a2); a3 = warp_sum_all(a3);
    __shared__ float red[8][4];
    int wid = threadIdx.x >> 5;
    if ((threadIdx.x & 31) == 0) { red[wid][0]=a0; red[wid][1]=a1; red[wid][2]=a2; red[wid][3]=a3; }
    __syncthreads();
    if (threadIdx.x < 4) {
        float s = 0.f;
        #pragma unroll
        for (int w8 = 0; w8 < 8; w8++) s += red[w8][threadIdx.x];
        if (bias) s += __ldg(bias + i);
        y[(size_t)threadIdx.x * N + i] = s;
    }
}
__global__ void __launch_bounds__(256) gemv_wo(const float* __restrict__ Wo) {
    gemv4_body<4>(Wo, d_attn_out, d_y1, nullptr, NHID, NHID);
}
__global__ void __launch_bounds__(256) gemv_w2(const float* __restrict__ W2) {
    gemv4_body<12>(W2, d_cbuf, d_y2, nullptr, MLPDIM, NHID);
}
__global__ void __launch_bounds__(256) gemv_ws(const float* __restrict__ Ws,
                                               const float* __restrict__ bias,
                                               float* __restrict__ out) {
    gemv4_body<4>(Ws, d_ln2, out, bias, NHID, 2048);
}

// ---------------- fused W0/W1 + SiLU (float4 loads) ----------------
__global__ void __launch_bounds__(256) mlp_kernel(const float* __restrict__ W0,
                                                  const float* __restrict__ W1) {
    int i = blockIdx.x;
    const float4* w04 = (const float4*)(W0 + (size_t)i * NHID);
    const float4* w14 = (const float4*)(W1 + (size_t)i * NHID);
    const float4* x4  = (const float4*)d_ln1;
    float a[4] = {0,0,0,0}, g[4] = {0,0,0,0};
    #pragma unroll
    for (int ii = 0; ii < 4; ii++) {
        int k = threadIdx.x + ii * 256;
        float4 v0 = __ldg(w04 + k), v1 = __ldg(w14 + k);
        #pragma unroll
        for (int b = 0; b < 4; b++) {
            float4 xv = __ldg(x4 + b * (NHID/4) + k);
            a[b] += v0.x*xv.x + v0.y*xv.y + v0.z*xv.z + v0.w*xv.w;
            g[b] += v1.x*xv.x + v1.y*xv.y + v1.z*xv.z + v1.w*xv.w;
        }
    }
    __shared__ float ra[8][4], rg[8][4];
    int wid = threadIdx.x >> 5;
    #pragma unroll
    for (int b = 0; b < 4; b++) { a[b] = warp_sum_all(a[b]); g[b] = warp_sum_all(g[b]); }
    if ((threadIdx.x & 31) == 0) {
        #pragma unroll
        for (int b = 0; b < 4; b++) { ra[wid][b] = a[b]; rg[wid][b] = g[b]; }
    }
    __syncthreads();
    if (threadIdx.x < 4) {
        float sa = 0.f, sg = 0.f;
        #pragma unroll
        for (int w = 0; w < 8; w++) { sa += ra[w][threadIdx.x]; sg += rg[w][threadIdx.x]; }
        float si = sg / (1.f + expf(-sg));
        d_cbuf[(size_t)threadIdx.x * MLPDIM + i] = sa * si;
    }
}

// ---------------- layernorm ----------------
template<int STAGE>
__global__ void __launch_bounds__(256) ln_kernel(const float* __restrict__ g,
                                                 const float* __restrict__ bb) {
    const float* x = (STAGE == 0 ? d_y1 : d_y2) + (size_t)blockIdx.x * NHID;
    float* y       = (STAGE == 0 ? d_ln1 : d_ln2) + (size_t)blockIdx.x * NHID;
    float s = 0.f, s2 = 0.f;
    for (int k = threadIdx.x; k < NHID; k += 256) { float v = x[k]; s += v; s2 += v*v; }
    s = warp_sum_all(s); s2 = warp_sum_all(s2);
    __shared__ float rs[8], rs2[8];
    int wid = threadIdx.x >> 5;
    if ((threadIdx.x & 31) == 0) { rs[wid] = s; rs2[wid] = s2; }
    __syncthreads();
    if (threadIdx.x == 0) {
        float t = 0, t2 = 0;
        for (int w = 0; w < 8; w++) { t += rs[w]; t2 += rs2[w]; }
        rs[0] = t; rs2[0] = t2;
    }
    __syncthreads();
    float mu  = rs[0] / (float)NHID;
    float var = rs2[0] / (float)NHID - mu * mu;
    float inv = rsqrtf(var + 1e-5f);
    for (int k = threadIdx.x; k < NHID; k += 256)
        y[k] = (x[k] - mu) * inv * __ldg(g + k) + __ldg(bb + k);
}

// ---------------- launch ----------------
extern "C" void kernel_launch(void* const* d_in, const int* in_sizes, int n_in,
                              void* d_out, int out_size) {
    const float* hidden = (const float*)d_in[0];
    const float* q      = (const float*)d_in[1];
    const float* Wk     = (const float*)d_in[2];
    const float* Wv     = (const float*)d_in[3];
    const float* Wo     = (const float*)d_in[4];
    const float* W0     = (const float*)d_in[5];
    const float* W1     = (const float*)d_in[6];
    const float* W2     = (const float*)d_in[7];
    const float* Ws     = (const float*)d_in[8];
    const float* bs     = (const float*)d_in[9];
    const float* ln_g   = (const float*)d_in[10];
    const float* ln_b   = (const float*)d_in[11];
    float* out = (float*)d_out;

    cs_kernel<<<512, 256>>>();
    cvt_all<<<49152, 256>>>(hidden, Wv);
    wkt_kernel<<<dim3(128, 128), 256>>>(Wk);
    qrot_kernel<<<16384, 256>>>(q);
    agemm<<<dim3(32, 16, 32), 128>>>();           // A = Qrot @ Wk  (per head)
    scores_dot<<<2048, 256>>>();                  // S = X . A
    softmax_kernel<<<128, 256>>>();
    gemm_v<<<dim3(32, 64), 128>>>();              // V-GEMM + RoPE + attn@V partials
    attnv_reduce<<<64, 256>>>();
    gemv_wo<<<4096, 256>>>(Wo);
    ln_kernel<0><<<4, 256>>>(ln_g, ln_b);
    mlp_kernel<<<12288, 256>>>(W0, W1);
    gemv_w2<<<4096, 256>>>(W2);
    ln_kernel<1><<<4, 256>>>(ln_g, ln_b);
    gemv_ws<<<2048, 256>>>(Ws, bs, out);
}